// round 1
// baseline (speedup 1.0000x reference)
#include <cuda_runtime.h>
#include <math.h>

#define B_    4
#define T_    2048
#define H_    16
#define D_    128
#define ATTN_ 2048
#define BT_   (B_*T_)

// Scratch (allocation-free rule: __device__ globals)
__device__ float g_q[(size_t)BT_ * ATTN_];
__device__ float g_k[(size_t)BT_ * ATTN_];
__device__ float g_v[(size_t)BT_ * ATTN_];
__device__ float g_y[(size_t)BT_ * ATTN_];

// ---------------------------------------------------------------------------
// GEMM: C[m,n] = sum_k A[m,k] * W[n,k] + bias[n], optional fused RoPE epilogue.
// A: (M,K) row-major, W: (N,K) row-major. 128x128x8 tile, 256 threads, 8x8 micro.
// ---------------------------------------------------------------------------
template<bool ROPE>
__global__ __launch_bounds__(256) void gemm_bias_kernel(
    const float* __restrict__ A, const float* __restrict__ W,
    const float* __restrict__ bias, float* __restrict__ C,
    int M, int N, int K)
{
    __shared__ __align__(16) float Xs[8][132];
    __shared__ __align__(16) float Ws[8][132];

    const int tid = threadIdx.x;
    const int bm  = blockIdx.y * 128;
    const int bn  = blockIdx.x * 128;
    const int tx  = tid & 15;
    const int ty  = tid >> 4;
    const int lr  = tid >> 1;          // 0..127 : row within tile for loading
    const int lk  = (tid & 1) * 4;     // 0 or 4 : k-offset for loading

    const float* Ag = A + (size_t)(bm + lr) * K + lk;
    const float* Wg = W + (size_t)(bn + lr) * K + lk;

    float acc[8][8];
#pragma unroll
    for (int i = 0; i < 8; i++)
#pragma unroll
        for (int j = 0; j < 8; j++) acc[i][j] = 0.f;

    for (int kt = 0; kt < K; kt += 8) {
        float4 av = *(const float4*)(Ag + kt);
        float4 wv = *(const float4*)(Wg + kt);
        __syncthreads();
        Xs[lk+0][lr] = av.x; Xs[lk+1][lr] = av.y; Xs[lk+2][lr] = av.z; Xs[lk+3][lr] = av.w;
        Ws[lk+0][lr] = wv.x; Ws[lk+1][lr] = wv.y; Ws[lk+2][lr] = wv.z; Ws[lk+3][lr] = wv.w;
        __syncthreads();
#pragma unroll
        for (int kk = 0; kk < 8; kk++) {
            float a[8], b[8];
            *(float4*)(a)     = *(const float4*)&Xs[kk][ty*8];
            *(float4*)(a + 4) = *(const float4*)&Xs[kk][ty*8 + 4];
            *(float4*)(b)     = *(const float4*)&Ws[kk][tx*8];
            *(float4*)(b + 4) = *(const float4*)&Ws[kk][tx*8 + 4];
#pragma unroll
            for (int i = 0; i < 8; i++)
#pragma unroll
                for (int j = 0; j < 8; j++)
                    acc[i][j] += a[i] * b[j];
        }
    }

    // Epilogue: bias (+ RoPE for Q/K)
    const int n0 = bn + tx * 8;
    float bv[8];
    *(float4*)(bv)     = *(const float4*)&bias[n0];
    *(float4*)(bv + 4) = *(const float4*)&bias[n0 + 4];

    // log(10000)/128
    const float kFreq = 0.07195578415606394f;

#pragma unroll
    for (int i = 0; i < 8; i++) {
        const int m = bm + ty * 8 + i;
        float cv[8];
#pragma unroll
        for (int j = 0; j < 8; j++) cv[j] = acc[i][j] + bv[j];
        if (ROPE) {
            const float pos = (float)(m & (T_ - 1));
#pragma unroll
            for (int jp = 0; jp < 8; jp += 2) {
                const int dp = (n0 + jp) & (D_ - 1);    // even index within head
                const float inv = expf((float)dp * -kFreq);
                const float ang = pos * inv;
                float s, c;
                sincosf(ang, &s, &c);
                const float t1 = cv[jp], t2 = cv[jp + 1];
                cv[jp]     = t1 * c - t2 * s;
                cv[jp + 1] = t1 * s + t2 * c;
            }
        }
        float* Cp = C + (size_t)m * N + n0;
        *(float4*)(Cp)     = make_float4(cv[0], cv[1], cv[2], cv[3]);
        *(float4*)(Cp + 4) = make_float4(cv[4], cv[5], cv[6], cv[7]);
    }
}

// ---------------------------------------------------------------------------
// Causal flash attention, fp32. BM=BN=64, D=128, 256 threads.
// Layout in smem: Qs[64][132], Kst[128][65] (K transposed), Vs[64][132], Ss[64][65]
// Thread (rg,cg): rg=tid>>4, cg=tid&15. S rows rq=rg*4 (+0..3), S cols cq=cg*4,
// O cols co=cg*8. Row stats reduced over the 16 cg-lanes (lane-aligned groups).
// ---------------------------------------------------------------------------
#define FL_SMEM 117504
__global__ __launch_bounds__(256) void flash_kernel(
    const float* __restrict__ Q, const float* __restrict__ K,
    const float* __restrict__ V, float* __restrict__ O)
{
    extern __shared__ __align__(16) float sm[];
    float* Qs  = sm;                       // 64*132 = 8448
    float* Kst = sm + 8448;                // 128*65 = 8320
    float* Vs  = sm + 8448 + 8320;         // 64*132 = 8448
    float* Ss  = sm + 8448 + 8320 + 8448;  // 64*65  = 4160

    const int qt  = blockIdx.x;
    const int h   = blockIdx.y;
    const int b   = blockIdx.z;
    const int tid = threadIdx.x;

    const float* qbase = Q + ((size_t)(b * T_ + qt * 64)) * ATTN_ + h * D_;

    for (int e = tid; e < 2048; e += 256) {
        int r = e >> 5, c4 = (e & 31) << 2;
        *(float4*)&Qs[r * 132 + c4] = *(const float4*)(qbase + (size_t)r * ATTN_ + c4);
    }

    const int rg = tid >> 4, cg = tid & 15;
    const int rq = rg << 2, cq = cg << 2, co = cg << 3;

    float m_i[4], l_i[4], Oacc[4][8];
#pragma unroll
    for (int i = 0; i < 4; i++) {
        m_i[i] = -1e30f; l_i[i] = 0.f;
#pragma unroll
        for (int j2 = 0; j2 < 8; j2++) Oacc[i][j2] = 0.f;
    }

    const float scale = 0.08838834764831843f;  // 1/sqrt(128)

    for (int j = 0; j <= qt; j++) {
        __syncthreads();   // protect Kst/Vs/Ss from previous iteration readers
        const float* kbase = K + ((size_t)(b * T_ + j * 64)) * ATTN_ + h * D_;
        const float* vbase = V + ((size_t)(b * T_ + j * 64)) * ATTN_ + h * D_;
        for (int e = tid; e < 8192; e += 256) {
            int kr = e >> 7, kk = e & 127;
            Kst[kk * 65 + kr] = kbase[(size_t)kr * ATTN_ + kk];   // conflict-free stores
        }
        for (int e = tid; e < 2048; e += 256) {
            int r = e >> 5, c4 = (e & 31) << 2;
            *(float4*)&Vs[r * 132 + c4] = *(const float4*)(vbase + (size_t)r * ATTN_ + c4);
        }
        __syncthreads();

        // S = Q K^T for this tile: 4x4 per thread
        float acc[4][4];
#pragma unroll
        for (int i = 0; i < 4; i++)
#pragma unroll
            for (int c = 0; c < 4; c++) acc[i][c] = 0.f;

#pragma unroll 4
        for (int kk = 0; kk < 128; kk++) {
            const float a0 = Qs[(rq + 0) * 132 + kk];
            const float a1 = Qs[(rq + 1) * 132 + kk];
            const float a2 = Qs[(rq + 2) * 132 + kk];
            const float a3 = Qs[(rq + 3) * 132 + kk];
            const float b0 = Kst[kk * 65 + cq + 0];
            const float b1 = Kst[kk * 65 + cq + 1];
            const float b2 = Kst[kk * 65 + cq + 2];
            const float b3 = Kst[kk * 65 + cq + 3];
            acc[0][0] += a0 * b0; acc[0][1] += a0 * b1; acc[0][2] += a0 * b2; acc[0][3] += a0 * b3;
            acc[1][0] += a1 * b0; acc[1][1] += a1 * b1; acc[1][2] += a1 * b2; acc[1][3] += a1 * b3;
            acc[2][0] += a2 * b0; acc[2][1] += a2 * b1; acc[2][2] += a2 * b2; acc[2][3] += a2 * b3;
            acc[3][0] += a3 * b0; acc[3][1] += a3 * b1; acc[3][2] += a3 * b2; acc[3][3] += a3 * b3;
        }

        const bool diag = (j == qt);
#pragma unroll
        for (int i = 0; i < 4; i++) {
            const int lrow = rq + i;
            float s4[4];
            float mx = -1e30f;
#pragma unroll
            for (int c = 0; c < 4; c++) {
                float sv = acc[i][c] * scale;
                if (diag && (cq + c > lrow)) sv = -1e30f;
                s4[c] = sv;
                mx = fmaxf(mx, sv);
            }
#pragma unroll
            for (int o = 1; o < 16; o <<= 1)
                mx = fmaxf(mx, __shfl_xor_sync(0xffffffffu, mx, o));
            const float m_new = fmaxf(m_i[i], mx);
            const float alpha = __expf(m_i[i] - m_new);
            float lsum = 0.f;
#pragma unroll
            for (int c = 0; c < 4; c++) {
                const float p = __expf(s4[c] - m_new);
                Ss[lrow * 65 + cq + c] = p;
                lsum += p;
            }
#pragma unroll
            for (int o = 1; o < 16; o <<= 1)
                lsum += __shfl_xor_sync(0xffffffffu, lsum, o);
            l_i[i] = l_i[i] * alpha + lsum;
            m_i[i] = m_new;
#pragma unroll
            for (int j2 = 0; j2 < 8; j2++) Oacc[i][j2] *= alpha;
        }
        __syncthreads();

        // O += P @ V : thread owns rows rq..rq+3, output cols co..co+7
#pragma unroll 2
        for (int c = 0; c < 64; c++) {
            const float4 v0 = *(const float4*)&Vs[c * 132 + co];
            const float4 v1 = *(const float4*)&Vs[c * 132 + co + 4];
            const float p0 = Ss[(rq + 0) * 65 + c];
            const float p1 = Ss[(rq + 1) * 65 + c];
            const float p2 = Ss[(rq + 2) * 65 + c];
            const float p3 = Ss[(rq + 3) * 65 + c];
            Oacc[0][0] += p0 * v0.x; Oacc[0][1] += p0 * v0.y; Oacc[0][2] += p0 * v0.z; Oacc[0][3] += p0 * v0.w;
            Oacc[0][4] += p0 * v1.x; Oacc[0][5] += p0 * v1.y; Oacc[0][6] += p0 * v1.z; Oacc[0][7] += p0 * v1.w;
            Oacc[1][0] += p1 * v0.x; Oacc[1][1] += p1 * v0.y; Oacc[1][2] += p1 * v0.z; Oacc[1][3] += p1 * v0.w;
            Oacc[1][4] += p1 * v1.x; Oacc[1][5] += p1 * v1.y; Oacc[1][6] += p1 * v1.z; Oacc[1][7] += p1 * v1.w;
            Oacc[2][0] += p2 * v0.x; Oacc[2][1] += p2 * v0.y; Oacc[2][2] += p2 * v0.z; Oacc[2][3] += p2 * v0.w;
            Oacc[2][4] += p2 * v1.x; Oacc[2][5] += p2 * v1.y; Oacc[2][6] += p2 * v1.z; Oacc[2][7] += p2 * v1.w;
            Oacc[3][0] += p3 * v0.x; Oacc[3][1] += p3 * v0.y; Oacc[3][2] += p3 * v0.z; Oacc[3][3] += p3 * v0.w;
            Oacc[3][4] += p3 * v1.x; Oacc[3][5] += p3 * v1.y; Oacc[3][6] += p3 * v1.z; Oacc[3][7] += p3 * v1.w;
        }
    }

    float* obase = O + ((size_t)(b * T_ + qt * 64)) * ATTN_ + h * D_;
#pragma unroll
    for (int i = 0; i < 4; i++) {
        const float invl = 1.0f / l_i[i];
        float* op = obase + (size_t)(rq + i) * ATTN_ + co;
        *(float4*)(op)     = make_float4(Oacc[i][0] * invl, Oacc[i][1] * invl,
                                         Oacc[i][2] * invl, Oacc[i][3] * invl);
        *(float4*)(op + 4) = make_float4(Oacc[i][4] * invl, Oacc[i][5] * invl,
                                         Oacc[i][6] * invl, Oacc[i][7] * invl);
    }
}

// ---------------------------------------------------------------------------
extern "C" void kernel_launch(void* const* d_in, const int* in_sizes, int n_in,
                              void* d_out, int out_size)
{
    const float* x    = (const float*)d_in[0];
    // d_in[1], d_in[2] = freqs_cos/sin : UNUSED (reference recomputes from FREQ_BASE)
    const float* wq_w = (const float*)d_in[3];
    const float* wq_b = (const float*)d_in[4];
    const float* wk_w = (const float*)d_in[5];
    const float* wk_b = (const float*)d_in[6];
    const float* wv_w = (const float*)d_in[7];
    const float* wv_b = (const float*)d_in[8];
    const float* wo_w = (const float*)d_in[9];
    const float* wo_b = (const float*)d_in[10];
    float* out = (float*)d_out;

    float *qp, *kp, *vp, *yp;
    cudaGetSymbolAddress((void**)&qp, g_q);
    cudaGetSymbolAddress((void**)&kp, g_k);
    cudaGetSymbolAddress((void**)&vp, g_v);
    cudaGetSymbolAddress((void**)&yp, g_y);

    dim3 gg(ATTN_ / 128, BT_ / 128);   // (16, 64)

    gemm_bias_kernel<true ><<<gg, 256>>>(x,  wq_w, wq_b, qp, BT_, ATTN_, ATTN_);
    gemm_bias_kernel<true ><<<gg, 256>>>(x,  wk_w, wk_b, kp, BT_, ATTN_, ATTN_);
    gemm_bias_kernel<false><<<gg, 256>>>(x,  wv_w, wv_b, vp, BT_, ATTN_, ATTN_);

    cudaFuncSetAttribute(flash_kernel, cudaFuncAttributeMaxDynamicSharedMemorySize, FL_SMEM);
    flash_kernel<<<dim3(T_ / 64, H_, B_), 256, FL_SMEM>>>(qp, kp, vp, yp);

    gemm_bias_kernel<false><<<gg, 256>>>(yp, wo_w, wo_b, out, BT_, ATTN_, ATTN_);
}

// round 3
// speedup vs baseline: 1.7019x; 1.7019x over previous
#include <cuda_runtime.h>
#include <cuda_bf16.h>
#include <math.h>
#include <stdint.h>

#define B_    4
#define T_    2048
#define H_    16
#define D_    128
#define ATTN_ 2048
#define BT_   (B_*T_)

// ---------------------------------------------------------------------------
// Scratch (__device__ globals; no allocation allowed)
// ---------------------------------------------------------------------------
__device__ float g_q[(size_t)BT_ * ATTN_];
__device__ float g_k[(size_t)BT_ * ATTN_];
__device__ float g_v[(size_t)BT_ * ATTN_];
__device__ float g_y[(size_t)BT_ * ATTN_];
__device__ __nv_bfloat16 g_xh[(size_t)BT_ * ATTN_];
__device__ __nv_bfloat16 g_xl[(size_t)BT_ * ATTN_];
__device__ __nv_bfloat16 g_yh[(size_t)BT_ * ATTN_];
__device__ __nv_bfloat16 g_yl[(size_t)BT_ * ATTN_];
__device__ __nv_bfloat16 g_wh[(size_t)4 * ATTN_ * ATTN_];
__device__ __nv_bfloat16 g_wl[(size_t)4 * ATTN_ * ATTN_];
__device__ float g_cosT[T_ * 64];
__device__ float g_sinT[T_ * 64];

// ---------------------------------------------------------------------------
// PTX helpers (all baseline sm_80-era PTX: valid under .target sm_103)
// ---------------------------------------------------------------------------
__device__ __forceinline__ uint32_t smem_u32(const void* p) {
    uint32_t a;
    asm("{ .reg .u64 t; cvta.to.shared.u64 t, %1; cvt.u32.u64 %0, t; }" : "=r"(a) : "l"(p));
    return a;
}

#define CP_ASYNC16(dst, src) \
    asm volatile("cp.async.cg.shared.global [%0], [%1], 16;" :: "r"(dst), "l"(src))
#define CP_COMMIT() asm volatile("cp.async.commit_group;" ::: "memory")
#define CP_WAIT(n)  asm volatile("cp.async.wait_group %0;" :: "n"(n) : "memory")

__device__ __forceinline__ void ldsm4(uint32_t* r, uint32_t addr) {
    asm volatile("ldmatrix.sync.aligned.m8n8.x4.shared.b16 {%0,%1,%2,%3}, [%4];"
                 : "=r"(r[0]), "=r"(r[1]), "=r"(r[2]), "=r"(r[3]) : "r"(addr));
}

__device__ __forceinline__ void mma16816(float* c, const uint32_t* a,
                                         uint32_t b0, uint32_t b1) {
    asm volatile(
        "mma.sync.aligned.m16n8k16.row.col.f32.bf16.bf16.f32 "
        "{%0,%1,%2,%3}, {%4,%5,%6,%7}, {%8,%9}, {%0,%1,%2,%3};"
        : "+f"(c[0]), "+f"(c[1]), "+f"(c[2]), "+f"(c[3])
        : "r"(a[0]), "r"(a[1]), "r"(a[2]), "r"(a[3]), "r"(b0), "r"(b1));
}

// ---------------------------------------------------------------------------
// Small elementwise kernels
// ---------------------------------------------------------------------------
__global__ void rope_table_kernel(float* __restrict__ cosT, float* __restrict__ sinT) {
    const int t = blockIdx.x;
    const int i = threadIdx.x;  // pair index 0..63
    const float kFreq = 0.07195578415606394f;  // ln(10000)/128
    const float inv = expf((float)(2 * i) * -kFreq);
    const float ang = (float)t * inv;
    float s, c;
    sincosf(ang, &s, &c);
    cosT[t * 64 + i] = c;
    sinT[t * 64 + i] = s;
}

__global__ void split_kernel(const float4* __restrict__ src,
                             __nv_bfloat162* __restrict__ hi,
                             __nv_bfloat162* __restrict__ lo, int n4) {
    int i = blockIdx.x * blockDim.x + threadIdx.x;
    if (i >= n4) return;
    float4 v = src[i];
    __nv_bfloat16 h0 = __float2bfloat16(v.x);
    __nv_bfloat16 h1 = __float2bfloat16(v.y);
    __nv_bfloat16 h2 = __float2bfloat16(v.z);
    __nv_bfloat16 h3 = __float2bfloat16(v.w);
    __nv_bfloat16 l0 = __float2bfloat16(v.x - __bfloat162float(h0));
    __nv_bfloat16 l1 = __float2bfloat16(v.y - __bfloat162float(h1));
    __nv_bfloat16 l2 = __float2bfloat16(v.z - __bfloat162float(h2));
    __nv_bfloat16 l3 = __float2bfloat16(v.w - __bfloat162float(h3));
    hi[2 * i]     = __halves2bfloat162(h0, h1);
    hi[2 * i + 1] = __halves2bfloat162(h2, h3);
    lo[2 * i]     = __halves2bfloat162(l0, l1);
    lo[2 * i + 1] = __halves2bfloat162(l2, l3);
}

// ---------------------------------------------------------------------------
// bf16x3 GEMM via mma.sync: C[M,N] = (Ah+Al)(Wh+Wl)^T + bias (+RoPE)
// BM=BN=128, BK=64. 256 threads = 8 warps (2 M x 4 N), warp tile 64x32.
// smem per stage: Ah,Al,Wh,Wl each 128 x 72(pad) bf16 = 18432 B -> 73728 B.
// Double-buffered cp.async.
// ---------------------------------------------------------------------------
static constexpr int GBM = 128, GBN = 128, GBK = 64;
static constexpr int LDS_ = 72;                   // padded row, elems
static constexpr int ARR_B = 128 * LDS_ * 2;      // 18432
static constexpr int STAGE_B = 4 * ARR_B;         // 73728
static constexpr int GEMM_SMEM = 2 * STAGE_B;     // 147456

template <bool ROPE>
__global__ void __launch_bounds__(256, 1) mma_gemm(
    const __nv_bfloat16* __restrict__ Ah, const __nv_bfloat16* __restrict__ Al,
    const __nv_bfloat16* __restrict__ Wh, const __nv_bfloat16* __restrict__ Wl,
    const float* __restrict__ bias, float* __restrict__ C,
    const float* __restrict__ cosT, const float* __restrict__ sinT)
{
    extern __shared__ char dsm[];
    const uint32_t sBase = smem_u32(dsm);

    const int tid  = threadIdx.x;
    const int wid  = tid >> 5;
    const int lane = tid & 31;
    const int wm   = (wid >> 2) * 64;   // warp M offset in tile
    const int wn   = (wid & 3) * 32;    // warp N offset in tile
    const int bm   = blockIdx.y * GBM;
    const int bn   = blockIdx.x * GBN;

    // Loader decomposition: 4096 16B-chunks/stage, 16 per thread.
    const int cc    = tid & 7;        // 16B chunk within row
    const int rbase = tid >> 3;       // 0..31

    const __nv_bfloat16* gb[4];
    gb[0] = Ah + (size_t)bm * ATTN_;
    gb[1] = Al + (size_t)bm * ATTN_;
    gb[2] = Wh + (size_t)bn * ATTN_;
    gb[3] = Wl + (size_t)bn * ATTN_;

    float acc[4][4][4];
#pragma unroll
    for (int mt = 0; mt < 4; mt++)
#pragma unroll
        for (int nt = 0; nt < 4; nt++)
#pragma unroll
            for (int e = 0; e < 4; e++) acc[mt][nt][e] = 0.f;

    // ldmatrix per-lane address components
    const int lr = lane & 15;
    const int lc = (lane >> 4) << 3;

    const int NIT = ATTN_ / GBK;   // 32

    // Prologue: load stage 0
    {
        const int k0 = 0;
#pragma unroll
        for (int i = 0; i < 16; i++) {
            const int arr = i >> 2;
            const int r = ((i & 3) << 5) + rbase;
            const uint32_t dst = sBase + arr * ARR_B + r * (LDS_ * 2) + cc * 16;
            const __nv_bfloat16* src = gb[arr] + (size_t)r * ATTN_ + k0 + cc * 8;
            CP_ASYNC16(dst, src);
        }
        CP_COMMIT();
    }

    for (int kt = 0; kt < NIT; kt++) {
        if (kt + 1 < NIT) {
            const int k0 = (kt + 1) * GBK;
            const uint32_t st = sBase + ((kt + 1) & 1) * STAGE_B;
#pragma unroll
            for (int i = 0; i < 16; i++) {
                const int arr = i >> 2;
                const int r = ((i & 3) << 5) + rbase;
                const uint32_t dst = st + arr * ARR_B + r * (LDS_ * 2) + cc * 16;
                const __nv_bfloat16* src = gb[arr] + (size_t)r * ATTN_ + k0 + cc * 8;
                CP_ASYNC16(dst, src);
            }
            CP_COMMIT();
            CP_WAIT(1);
        } else {
            CP_WAIT(0);
        }
        __syncthreads();

        const uint32_t st  = sBase + (kt & 1) * STAGE_B;
        const uint32_t sAh = st;
        const uint32_t sAl = st + ARR_B;
        const uint32_t sWh = st + 2 * ARR_B;
        const uint32_t sWl = st + 3 * ARR_B;

#pragma unroll
        for (int ks = 0; ks < 4; ks++) {
            const int kc = ks * 16 + lc;
            uint32_t af[4][4], whf[2][4], wlf[2][4];
#pragma unroll
            for (int mt = 0; mt < 4; mt++)
                ldsm4(af[mt], sAh + ((wm + mt * 16 + lr) * LDS_ + kc) * 2);
#pragma unroll
            for (int g = 0; g < 2; g++)
                ldsm4(whf[g], sWh + ((wn + g * 16 + lr) * LDS_ + kc) * 2);
#pragma unroll
            for (int g = 0; g < 2; g++)
                ldsm4(wlf[g], sWl + ((wn + g * 16 + lr) * LDS_ + kc) * 2);

            // Ah * Wh
#pragma unroll
            for (int mt = 0; mt < 4; mt++)
#pragma unroll
                for (int nt = 0; nt < 4; nt++)
                    mma16816(acc[mt][nt], af[mt], whf[nt >> 1][nt & 1], whf[nt >> 1][(nt & 1) + 2]);
            // Ah * Wl
#pragma unroll
            for (int mt = 0; mt < 4; mt++)
#pragma unroll
                for (int nt = 0; nt < 4; nt++)
                    mma16816(acc[mt][nt], af[mt], wlf[nt >> 1][nt & 1], wlf[nt >> 1][(nt & 1) + 2]);
            // Al * Wh
#pragma unroll
            for (int mt = 0; mt < 4; mt++)
                ldsm4(af[mt], sAl + ((wm + mt * 16 + lr) * LDS_ + kc) * 2);
#pragma unroll
            for (int mt = 0; mt < 4; mt++)
#pragma unroll
                for (int nt = 0; nt < 4; nt++)
                    mma16816(acc[mt][nt], af[mt], whf[nt >> 1][nt & 1], whf[nt >> 1][(nt & 1) + 2]);
        }
        __syncthreads();
    }

    // Epilogue: bias + optional RoPE, fp32 store.
    const int rr = lane >> 2;          // 0..7
    const int nn = (lane & 3) * 2;     // even col
#pragma unroll
    for (int mt = 0; mt < 4; mt++) {
#pragma unroll
        for (int half = 0; half < 2; half++) {
            const int m = bm + wm + mt * 16 + rr + half * 8;
            const int pos = m & (T_ - 1);
            float* Crow = C + (size_t)m * ATTN_;
#pragma unroll
            for (int nt = 0; nt < 4; nt++) {
                const int n0 = bn + wn + nt * 8 + nn;
                float v0 = acc[mt][nt][half * 2 + 0] + __ldg(&bias[n0]);
                float v1 = acc[mt][nt][half * 2 + 1] + __ldg(&bias[n0 + 1]);
                if (ROPE) {
                    const int pi = (n0 & (D_ - 1)) >> 1;
                    const float cv = __ldg(&cosT[pos * 64 + pi]);
                    const float sv = __ldg(&sinT[pos * 64 + pi]);
                    const float t1 = v0, t2 = v1;
                    v0 = t1 * cv - t2 * sv;
                    v1 = t1 * sv + t2 * cv;
                }
                *(float2*)(Crow + n0) = make_float2(v0, v1);
            }
        }
    }
}

// ---------------------------------------------------------------------------
// Causal flash attention, fp32 (unchanged: known good from round 1).
// ---------------------------------------------------------------------------
#define FL_SMEM 117504
__global__ __launch_bounds__(256) void flash_kernel(
    const float* __restrict__ Q, const float* __restrict__ K,
    const float* __restrict__ V, float* __restrict__ O)
{
    extern __shared__ __align__(16) float sm[];
    float* Qs  = sm;                       // 64*132
    float* Kst = sm + 8448;                // 128*65
    float* Vs  = sm + 8448 + 8320;         // 64*132
    float* Ss  = sm + 8448 + 8320 + 8448;  // 64*65

    const int qt  = blockIdx.x;
    const int h   = blockIdx.y;
    const int b   = blockIdx.z;
    const int tid = threadIdx.x;

    const float* qbase = Q + ((size_t)(b * T_ + qt * 64)) * ATTN_ + h * D_;

    for (int e = tid; e < 2048; e += 256) {
        int r = e >> 5, c4 = (e & 31) << 2;
        *(float4*)&Qs[r * 132 + c4] = *(const float4*)(qbase + (size_t)r * ATTN_ + c4);
    }

    const int rg = tid >> 4, cg = tid & 15;
    const int rq = rg << 2, cq = cg << 2, co = cg << 3;

    float m_i[4], l_i[4], Oacc[4][8];
#pragma unroll
    for (int i = 0; i < 4; i++) {
        m_i[i] = -1e30f; l_i[i] = 0.f;
#pragma unroll
        for (int j2 = 0; j2 < 8; j2++) Oacc[i][j2] = 0.f;
    }

    const float scale = 0.08838834764831843f;

    for (int j = 0; j <= qt; j++) {
        __syncthreads();
        const float* kbase = K + ((size_t)(b * T_ + j * 64)) * ATTN_ + h * D_;
        const float* vbase = V + ((size_t)(b * T_ + j * 64)) * ATTN_ + h * D_;
        for (int e = tid; e < 8192; e += 256) {
            int kr = e >> 7, kk = e & 127;
            Kst[kk * 65 + kr] = kbase[(size_t)kr * ATTN_ + kk];
        }
        for (int e = tid; e < 2048; e += 256) {
            int r = e >> 5, c4 = (e & 31) << 2;
            *(float4*)&Vs[r * 132 + c4] = *(const float4*)(vbase + (size_t)r * ATTN_ + c4);
        }
        __syncthreads();

        float acc[4][4];
#pragma unroll
        for (int i = 0; i < 4; i++)
#pragma unroll
            for (int c = 0; c < 4; c++) acc[i][c] = 0.f;

#pragma unroll 4
        for (int kk = 0; kk < 128; kk++) {
            const float a0 = Qs[(rq + 0) * 132 + kk];
            const float a1 = Qs[(rq + 1) * 132 + kk];
            const float a2 = Qs[(rq + 2) * 132 + kk];
            const float a3 = Qs[(rq + 3) * 132 + kk];
            const float b0 = Kst[kk * 65 + cq + 0];
            const float b1 = Kst[kk * 65 + cq + 1];
            const float b2 = Kst[kk * 65 + cq + 2];
            const float b3 = Kst[kk * 65 + cq + 3];
            acc[0][0] += a0 * b0; acc[0][1] += a0 * b1; acc[0][2] += a0 * b2; acc[0][3] += a0 * b3;
            acc[1][0] += a1 * b0; acc[1][1] += a1 * b1; acc[1][2] += a1 * b2; acc[1][3] += a1 * b3;
            acc[2][0] += a2 * b0; acc[2][1] += a2 * b1; acc[2][2] += a2 * b2; acc[2][3] += a2 * b3;
            acc[3][0] += a3 * b0; acc[3][1] += a3 * b1; acc[3][2] += a3 * b2; acc[3][3] += a3 * b3;
        }

        const bool diag = (j == qt);
#pragma unroll
        for (int i = 0; i < 4; i++) {
            const int lrow = rq + i;
            float s4[4];
            float mx = -1e30f;
#pragma unroll
            for (int c = 0; c < 4; c++) {
                float sv = acc[i][c] * scale;
                if (diag && (cq + c > lrow)) sv = -1e30f;
                s4[c] = sv;
                mx = fmaxf(mx, sv);
            }
#pragma unroll
            for (int o = 1; o < 16; o <<= 1)
                mx = fmaxf(mx, __shfl_xor_sync(0xffffffffu, mx, o));
            const float m_new = fmaxf(m_i[i], mx);
            const float alpha = __expf(m_i[i] - m_new);
            float lsum = 0.f;
#pragma unroll
            for (int c = 0; c < 4; c++) {
                const float p = __expf(s4[c] - m_new);
                Ss[lrow * 65 + cq + c] = p;
                lsum += p;
            }
#pragma unroll
            for (int o = 1; o < 16; o <<= 1)
                lsum += __shfl_xor_sync(0xffffffffu, lsum, o);
            l_i[i] = l_i[i] * alpha + lsum;
            m_i[i] = m_new;
#pragma unroll
            for (int j2 = 0; j2 < 8; j2++) Oacc[i][j2] *= alpha;
        }
        __syncthreads();

#pragma unroll 2
        for (int c = 0; c < 64; c++) {
            const float4 v0 = *(const float4*)&Vs[c * 132 + co];
            const float4 v1 = *(const float4*)&Vs[c * 132 + co + 4];
            const float p0 = Ss[(rq + 0) * 65 + c];
            const float p1 = Ss[(rq + 1) * 65 + c];
            const float p2 = Ss[(rq + 2) * 65 + c];
            const float p3 = Ss[(rq + 3) * 65 + c];
            Oacc[0][0] += p0 * v0.x; Oacc[0][1] += p0 * v0.y; Oacc[0][2] += p0 * v0.z; Oacc[0][3] += p0 * v0.w;
            Oacc[0][4] += p0 * v1.x; Oacc[0][5] += p0 * v1.y; Oacc[0][6] += p0 * v1.z; Oacc[0][7] += p0 * v1.w;
            Oacc[1][0] += p1 * v0.x; Oacc[1][1] += p1 * v0.y; Oacc[1][2] += p1 * v0.z; Oacc[1][3] += p1 * v0.w;
            Oacc[1][4] += p1 * v1.x; Oacc[1][5] += p1 * v1.y; Oacc[1][6] += p1 * v1.z; Oacc[1][7] += p1 * v1.w;
            Oacc[2][0] += p2 * v0.x; Oacc[2][1] += p2 * v0.y; Oacc[2][2] += p2 * v0.z; Oacc[2][3] += p2 * v0.w;
            Oacc[2][4] += p2 * v1.x; Oacc[2][5] += p2 * v1.y; Oacc[2][6] += p2 * v1.z; Oacc[2][7] += p2 * v1.w;
            Oacc[3][0] += p3 * v0.x; Oacc[3][1] += p3 * v0.y; Oacc[3][2] += p3 * v0.z; Oacc[3][3] += p3 * v0.w;
            Oacc[3][4] += p3 * v1.x; Oacc[3][5] += p3 * v1.y; Oacc[3][6] += p3 * v1.z; Oacc[3][7] += p3 * v1.w;
        }
    }

    float* obase = O + ((size_t)(b * T_ + qt * 64)) * ATTN_ + h * D_;
#pragma unroll
    for (int i = 0; i < 4; i++) {
        const float invl = 1.0f / l_i[i];
        float* op = obase + (size_t)(rq + i) * ATTN_ + co;
        *(float4*)(op)     = make_float4(Oacc[i][0] * invl, Oacc[i][1] * invl,
                                         Oacc[i][2] * invl, Oacc[i][3] * invl);
        *(float4*)(op + 4) = make_float4(Oacc[i][4] * invl, Oacc[i][5] * invl,
                                         Oacc[i][6] * invl, Oacc[i][7] * invl);
    }
}

// ---------------------------------------------------------------------------
// Host side
// ---------------------------------------------------------------------------
extern "C" void kernel_launch(void* const* d_in, const int* in_sizes, int n_in,
                              void* d_out, int out_size)
{
    const float* x    = (const float*)d_in[0];
    const float* wq_w = (const float*)d_in[3];
    const float* wq_b = (const float*)d_in[4];
    const float* wk_w = (const float*)d_in[5];
    const float* wk_b = (const float*)d_in[6];
    const float* wv_w = (const float*)d_in[7];
    const float* wv_b = (const float*)d_in[8];
    const float* wo_w = (const float*)d_in[9];
    const float* wo_b = (const float*)d_in[10];
    float* out = (float*)d_out;

    float *qp, *kp, *vp, *yp, *cosp, *sinp;
    __nv_bfloat16 *xh, *xl, *yh, *yl, *wh, *wl;
    cudaGetSymbolAddress((void**)&qp, g_q);
    cudaGetSymbolAddress((void**)&kp, g_k);
    cudaGetSymbolAddress((void**)&vp, g_v);
    cudaGetSymbolAddress((void**)&yp, g_y);
    cudaGetSymbolAddress((void**)&cosp, g_cosT);
    cudaGetSymbolAddress((void**)&sinp, g_sinT);
    cudaGetSymbolAddress((void**)&xh, g_xh);
    cudaGetSymbolAddress((void**)&xl, g_xl);
    cudaGetSymbolAddress((void**)&yh, g_yh);
    cudaGetSymbolAddress((void**)&yl, g_yl);
    cudaGetSymbolAddress((void**)&wh, g_wh);
    cudaGetSymbolAddress((void**)&wl, g_wl);

    const size_t WSZ = (size_t)ATTN_ * ATTN_;
    __nv_bfloat16* whp[4] = {wh, wh + WSZ, wh + 2 * WSZ, wh + 3 * WSZ};
    __nv_bfloat16* wlp[4] = {wl, wl + WSZ, wl + 2 * WSZ, wl + 3 * WSZ};

    // RoPE tables + hi/lo splits
    rope_table_kernel<<<T_, 64>>>(cosp, sinp);
    const int n4x = BT_ * ATTN_ / 4;
    const int n4w = ATTN_ * ATTN_ / 4;
    split_kernel<<<n4x / 256, 256>>>((const float4*)x, (__nv_bfloat162*)xh,
                                     (__nv_bfloat162*)xl, n4x);
    const float* wsrc[4] = {wq_w, wk_w, wv_w, wo_w};
    for (int i = 0; i < 4; i++)
        split_kernel<<<n4w / 256, 256>>>((const float4*)wsrc[i],
                                         (__nv_bfloat162*)whp[i],
                                         (__nv_bfloat162*)wlp[i], n4w);

    cudaFuncSetAttribute(mma_gemm<true>,  cudaFuncAttributeMaxDynamicSharedMemorySize, GEMM_SMEM);
    cudaFuncSetAttribute(mma_gemm<false>, cudaFuncAttributeMaxDynamicSharedMemorySize, GEMM_SMEM);

    dim3 gg(ATTN_ / GBN, BT_ / GBM);  // (16, 64)
    mma_gemm<true ><<<gg, 256, GEMM_SMEM>>>(xh, xl, whp[0], wlp[0], wq_b, qp, cosp, sinp);
    mma_gemm<true ><<<gg, 256, GEMM_SMEM>>>(xh, xl, whp[1], wlp[1], wk_b, kp, cosp, sinp);
    mma_gemm<false><<<gg, 256, GEMM_SMEM>>>(xh, xl, whp[2], wlp[2], wv_b, vp, cosp, sinp);

    cudaFuncSetAttribute(flash_kernel, cudaFuncAttributeMaxDynamicSharedMemorySize, FL_SMEM);
    flash_kernel<<<dim3(T_ / 64, H_, B_), 256, FL_SMEM>>>(qp, kp, vp, yp);

    split_kernel<<<n4x / 256, 256>>>((const float4*)yp, (__nv_bfloat162*)yh,
                                     (__nv_bfloat162*)yl, n4x);
    mma_gemm<false><<<gg, 256, GEMM_SMEM>>>(yh, yl, whp[3], wlp[3], wo_b, out, cosp, sinp);
}

// round 4
// speedup vs baseline: 2.9206x; 1.7161x over previous
#include <cuda_runtime.h>
#include <cuda_bf16.h>
#include <math.h>
#include <stdint.h>

#define B_    4
#define T_    2048
#define H_    16
#define D_    128
#define ATTN_ 2048
#define BT_   (B_*T_)

// ---------------------------------------------------------------------------
// Scratch (__device__ globals; no allocation allowed)
// ---------------------------------------------------------------------------
__device__ float g_q[(size_t)BT_ * ATTN_];
__device__ float g_k[(size_t)BT_ * ATTN_];
__device__ float g_v[(size_t)BT_ * ATTN_];
__device__ float g_y[(size_t)BT_ * ATTN_];
__device__ __nv_bfloat16 g_xh[(size_t)BT_ * ATTN_];
__device__ __nv_bfloat16 g_xl[(size_t)BT_ * ATTN_];
__device__ __nv_bfloat16 g_yh[(size_t)BT_ * ATTN_];
__device__ __nv_bfloat16 g_yl[(size_t)BT_ * ATTN_];
__device__ __nv_bfloat16 g_wh[(size_t)4 * ATTN_ * ATTN_];
__device__ __nv_bfloat16 g_wl[(size_t)4 * ATTN_ * ATTN_];
__device__ float g_cosT[T_ * 64];
__device__ float g_sinT[T_ * 64];

// ---------------------------------------------------------------------------
// PTX helpers (baseline sm_80-era PTX only — sm_103 target has no tcgen05)
// ---------------------------------------------------------------------------
__device__ __forceinline__ uint32_t smem_u32(const void* p) {
    uint32_t a;
    asm("{ .reg .u64 t; cvta.to.shared.u64 t, %1; cvt.u32.u64 %0, t; }" : "=r"(a) : "l"(p));
    return a;
}

#define CP_ASYNC16(dst, src) \
    asm volatile("cp.async.cg.shared.global [%0], [%1], 16;" :: "r"(dst), "l"(src))
#define CP_COMMIT() asm volatile("cp.async.commit_group;" ::: "memory")
#define CP_WAIT(n)  asm volatile("cp.async.wait_group %0;" :: "n"(n) : "memory")

__device__ __forceinline__ void ldsm4(uint32_t* r, uint32_t addr) {
    asm volatile("ldmatrix.sync.aligned.m8n8.x4.shared.b16 {%0,%1,%2,%3}, [%4];"
                 : "=r"(r[0]), "=r"(r[1]), "=r"(r[2]), "=r"(r[3]) : "r"(addr));
}
__device__ __forceinline__ void ldsm4t(uint32_t* r, uint32_t addr) {
    asm volatile("ldmatrix.sync.aligned.m8n8.x4.trans.shared.b16 {%0,%1,%2,%3}, [%4];"
                 : "=r"(r[0]), "=r"(r[1]), "=r"(r[2]), "=r"(r[3]) : "r"(addr));
}

__device__ __forceinline__ void mma16816(float* c, const uint32_t* a,
                                         uint32_t b0, uint32_t b1) {
    asm volatile(
        "mma.sync.aligned.m16n8k16.row.col.f32.bf16.bf16.f32 "
        "{%0,%1,%2,%3}, {%4,%5,%6,%7}, {%8,%9}, {%0,%1,%2,%3};"
        : "+f"(c[0]), "+f"(c[1]), "+f"(c[2]), "+f"(c[3])
        : "r"(a[0]), "r"(a[1]), "r"(a[2]), "r"(a[3]), "r"(b0), "r"(b1));
}

__device__ __forceinline__ uint32_t packbf2(float a, float b) {
    __nv_bfloat162 t = __halves2bfloat162(__float2bfloat16(a), __float2bfloat16(b));
    return *(uint32_t*)&t;
}

// ---------------------------------------------------------------------------
// Small elementwise kernels
// ---------------------------------------------------------------------------
__global__ void rope_table_kernel(float* __restrict__ cosT, float* __restrict__ sinT) {
    const int t = blockIdx.x;
    const int i = threadIdx.x;
    const float kFreq = 0.07195578415606394f;  // ln(10000)/128
    const float inv = expf((float)(2 * i) * -kFreq);
    const float ang = (float)t * inv;
    float s, c;
    sincosf(ang, &s, &c);
    cosT[t * 64 + i] = c;
    sinT[t * 64 + i] = s;
}

__global__ void split_kernel(const float4* __restrict__ src,
                             __nv_bfloat162* __restrict__ hi,
                             __nv_bfloat162* __restrict__ lo, int n4) {
    int i = blockIdx.x * blockDim.x + threadIdx.x;
    if (i >= n4) return;
    float4 v = src[i];
    __nv_bfloat16 h0 = __float2bfloat16(v.x);
    __nv_bfloat16 h1 = __float2bfloat16(v.y);
    __nv_bfloat16 h2 = __float2bfloat16(v.z);
    __nv_bfloat16 h3 = __float2bfloat16(v.w);
    __nv_bfloat16 l0 = __float2bfloat16(v.x - __bfloat162float(h0));
    __nv_bfloat16 l1 = __float2bfloat16(v.y - __bfloat162float(h1));
    __nv_bfloat16 l2 = __float2bfloat16(v.z - __bfloat162float(h2));
    __nv_bfloat16 l3 = __float2bfloat16(v.w - __bfloat162float(h3));
    hi[2 * i]     = __halves2bfloat162(h0, h1);
    hi[2 * i + 1] = __halves2bfloat162(h2, h3);
    lo[2 * i]     = __halves2bfloat162(l0, l1);
    lo[2 * i + 1] = __halves2bfloat162(l2, l3);
}

// ---------------------------------------------------------------------------
// bf16x3 GEMM via mma.sync (unchanged from round 3, passing)
// ---------------------------------------------------------------------------
static constexpr int GBM = 128, GBN = 128, GBK = 64;
static constexpr int LDS_ = 72;
static constexpr int ARR_B = 128 * LDS_ * 2;
static constexpr int STAGE_B = 4 * ARR_B;
static constexpr int GEMM_SMEM = 2 * STAGE_B;

template <bool ROPE>
__global__ void __launch_bounds__(256, 1) mma_gemm(
    const __nv_bfloat16* __restrict__ Ah, const __nv_bfloat16* __restrict__ Al,
    const __nv_bfloat16* __restrict__ Wh, const __nv_bfloat16* __restrict__ Wl,
    const float* __restrict__ bias, float* __restrict__ C,
    const float* __restrict__ cosT, const float* __restrict__ sinT)
{
    extern __shared__ char dsm[];
    const uint32_t sBase = smem_u32(dsm);

    const int tid  = threadIdx.x;
    const int wid  = tid >> 5;
    const int lane = tid & 31;
    const int wm   = (wid >> 2) * 64;
    const int wn   = (wid & 3) * 32;
    const int bm   = blockIdx.y * GBM;
    const int bn   = blockIdx.x * GBN;

    const int cc    = tid & 7;
    const int rbase = tid >> 3;

    const __nv_bfloat16* gb[4];
    gb[0] = Ah + (size_t)bm * ATTN_;
    gb[1] = Al + (size_t)bm * ATTN_;
    gb[2] = Wh + (size_t)bn * ATTN_;
    gb[3] = Wl + (size_t)bn * ATTN_;

    float acc[4][4][4];
#pragma unroll
    for (int mt = 0; mt < 4; mt++)
#pragma unroll
        for (int nt = 0; nt < 4; nt++)
#pragma unroll
            for (int e = 0; e < 4; e++) acc[mt][nt][e] = 0.f;

    const int lr = lane & 15;
    const int lc = (lane >> 4) << 3;
    const int NIT = ATTN_ / GBK;

    {
#pragma unroll
        for (int i = 0; i < 16; i++) {
            const int arr = i >> 2;
            const int r = ((i & 3) << 5) + rbase;
            const uint32_t dst = sBase + arr * ARR_B + r * (LDS_ * 2) + cc * 16;
            const __nv_bfloat16* src = gb[arr] + (size_t)r * ATTN_ + cc * 8;
            CP_ASYNC16(dst, src);
        }
        CP_COMMIT();
    }

    for (int kt = 0; kt < NIT; kt++) {
        if (kt + 1 < NIT) {
            const int k0 = (kt + 1) * GBK;
            const uint32_t st = sBase + ((kt + 1) & 1) * STAGE_B;
#pragma unroll
            for (int i = 0; i < 16; i++) {
                const int arr = i >> 2;
                const int r = ((i & 3) << 5) + rbase;
                const uint32_t dst = st + arr * ARR_B + r * (LDS_ * 2) + cc * 16;
                const __nv_bfloat16* src = gb[arr] + (size_t)r * ATTN_ + k0 + cc * 8;
                CP_ASYNC16(dst, src);
            }
            CP_COMMIT();
            CP_WAIT(1);
        } else {
            CP_WAIT(0);
        }
        __syncthreads();

        const uint32_t st  = sBase + (kt & 1) * STAGE_B;
        const uint32_t sAh = st;
        const uint32_t sAl = st + ARR_B;
        const uint32_t sWh = st + 2 * ARR_B;
        const uint32_t sWl = st + 3 * ARR_B;

#pragma unroll
        for (int ks = 0; ks < 4; ks++) {
            const int kc = ks * 16 + lc;
            uint32_t af[4][4], whf[2][4], wlf[2][4];
#pragma unroll
            for (int mt = 0; mt < 4; mt++)
                ldsm4(af[mt], sAh + ((wm + mt * 16 + lr) * LDS_ + kc) * 2);
#pragma unroll
            for (int g = 0; g < 2; g++)
                ldsm4(whf[g], sWh + ((wn + g * 16 + lr) * LDS_ + kc) * 2);
#pragma unroll
            for (int g = 0; g < 2; g++)
                ldsm4(wlf[g], sWl + ((wn + g * 16 + lr) * LDS_ + kc) * 2);

#pragma unroll
            for (int mt = 0; mt < 4; mt++)
#pragma unroll
                for (int nt = 0; nt < 4; nt++)
                    mma16816(acc[mt][nt], af[mt], whf[nt >> 1][nt & 1], whf[nt >> 1][(nt & 1) + 2]);
#pragma unroll
            for (int mt = 0; mt < 4; mt++)
#pragma unroll
                for (int nt = 0; nt < 4; nt++)
                    mma16816(acc[mt][nt], af[mt], wlf[nt >> 1][nt & 1], wlf[nt >> 1][(nt & 1) + 2]);
#pragma unroll
            for (int mt = 0; mt < 4; mt++)
                ldsm4(af[mt], sAl + ((wm + mt * 16 + lr) * LDS_ + kc) * 2);
#pragma unroll
            for (int mt = 0; mt < 4; mt++)
#pragma unroll
                for (int nt = 0; nt < 4; nt++)
                    mma16816(acc[mt][nt], af[mt], whf[nt >> 1][nt & 1], whf[nt >> 1][(nt & 1) + 2]);
        }
        __syncthreads();
    }

    const int rr = lane >> 2;
    const int nn = (lane & 3) * 2;
#pragma unroll
    for (int mt = 0; mt < 4; mt++) {
#pragma unroll
        for (int half = 0; half < 2; half++) {
            const int m = bm + wm + mt * 16 + rr + half * 8;
            const int pos = m & (T_ - 1);
            float* Crow = C + (size_t)m * ATTN_;
#pragma unroll
            for (int nt = 0; nt < 4; nt++) {
                const int n0 = bn + wn + nt * 8 + nn;
                float v0 = acc[mt][nt][half * 2 + 0] + __ldg(&bias[n0]);
                float v1 = acc[mt][nt][half * 2 + 1] + __ldg(&bias[n0 + 1]);
                if (ROPE) {
                    const int pi = (n0 & (D_ - 1)) >> 1;
                    const float cv = __ldg(&cosT[pos * 64 + pi]);
                    const float sv = __ldg(&sinT[pos * 64 + pi]);
                    const float t1 = v0, t2 = v1;
                    v0 = t1 * cv - t2 * sv;
                    v1 = t1 * sv + t2 * cv;
                }
                *(float2*)(Crow + n0) = make_float2(v0, v1);
            }
        }
    }
}

// ---------------------------------------------------------------------------
// Tensor-core causal flash attention, bf16x3 split precision.
// CTA: 128 q-rows x full D=128. 8 warps, warp owns 16 q rows.
// KV tiles of 64. smem: Qh/Ql [128][136], Kh/Kl [64][136], Vh/Vl [64][136].
// S = QhKh + QhKl + QlKh (fp32 acc). P,V split hi/lo; O += PhVh + PhVl + PlVh.
// ---------------------------------------------------------------------------
static constexpr int FLD = 136;                    // padded row (elems)
static constexpr int FQ_B = 128 * FLD * 2;         // 34816
static constexpr int FK_B = 64 * FLD * 2;          // 17408
static constexpr int FL2_SMEM = 2 * FQ_B + 4 * FK_B;  // 139264

__global__ void __launch_bounds__(256, 1) flash_mma(
    const float* __restrict__ Q, const float* __restrict__ K,
    const float* __restrict__ V, float* __restrict__ O)
{
    extern __shared__ char fsm[];
    const uint32_t sb  = smem_u32(fsm);
    const uint32_t sQH = sb;
    const uint32_t sQL = sb + FQ_B;
    const uint32_t sKH = sb + 2 * FQ_B;
    const uint32_t sKL = sKH + FK_B;
    const uint32_t sVH = sKH + 2 * FK_B;
    const uint32_t sVL = sKH + 3 * FK_B;
    char* pQH = fsm;
    char* pQL = fsm + FQ_B;
    char* pKH = fsm + 2 * FQ_B;
    char* pKL = pKH + FK_B;
    char* pVH = pKH + 2 * FK_B;
    char* pVL = pKH + 3 * FK_B;

    const int qt = blockIdx.x, h = blockIdx.y, b = blockIdx.z;
    const int tid = threadIdx.x, wid = tid >> 5, lane = tid & 31;
    const int wm = wid * 16;
    const int lr = lane & 15;
    const int lcg = (lane >> 4) << 3;
    const float scale = 0.08838834764831843f;

    // ---- load Q (scaled), convert to hi/lo bf16 ----
    const float* qbase = Q + ((size_t)(b * T_ + qt * 128)) * ATTN_ + h * D_;
    for (int e = tid; e < 4096; e += 256) {
        const int r = e >> 5, c = (e & 31) << 2;
        float4 v = *(const float4*)(qbase + (size_t)r * ATTN_ + c);
        v.x *= scale; v.y *= scale; v.z *= scale; v.w *= scale;
        const __nv_bfloat16 h0 = __float2bfloat16(v.x), h1 = __float2bfloat16(v.y);
        const __nv_bfloat16 h2 = __float2bfloat16(v.z), h3 = __float2bfloat16(v.w);
        const size_t off = ((size_t)r * FLD + c) * 2;
        *(__nv_bfloat162*)(pQH + off)     = __halves2bfloat162(h0, h1);
        *(__nv_bfloat162*)(pQH + off + 4) = __halves2bfloat162(h2, h3);
        *(__nv_bfloat162*)(pQL + off)     = __halves2bfloat162(
            __float2bfloat16(v.x - __bfloat162float(h0)), __float2bfloat16(v.y - __bfloat162float(h1)));
        *(__nv_bfloat162*)(pQL + off + 4) = __halves2bfloat162(
            __float2bfloat16(v.z - __bfloat162float(h2)), __float2bfloat16(v.w - __bfloat162float(h3)));
    }

    float Oacc[16][4];
#pragma unroll
    for (int nt = 0; nt < 16; nt++)
#pragma unroll
        for (int e = 0; e < 4; e++) Oacc[nt][e] = 0.f;
    float m0 = -1e30f, m1 = -1e30f, l0 = 0.f, l1 = 0.f;

    const int grow0 = qt * 128 + wm + (lane >> 2);
    const int grow1 = grow0 + 8;
    const int nkv = 2 * qt + 2;

    for (int j = 0; j < nkv; j++) {
        __syncthreads();
        // ---- load K,V tile, convert to hi/lo ----
        const float* kbase = K + ((size_t)(b * T_ + j * 64)) * ATTN_ + h * D_;
        const float* vbase = V + ((size_t)(b * T_ + j * 64)) * ATTN_ + h * D_;
        for (int e = tid; e < 2048; e += 256) {
            const int r = e >> 5, c = (e & 31) << 2;
            const size_t off = ((size_t)r * FLD + c) * 2;
            float4 kv = *(const float4*)(kbase + (size_t)r * ATTN_ + c);
            __nv_bfloat16 a0 = __float2bfloat16(kv.x), a1 = __float2bfloat16(kv.y);
            __nv_bfloat16 a2 = __float2bfloat16(kv.z), a3 = __float2bfloat16(kv.w);
            *(__nv_bfloat162*)(pKH + off)     = __halves2bfloat162(a0, a1);
            *(__nv_bfloat162*)(pKH + off + 4) = __halves2bfloat162(a2, a3);
            *(__nv_bfloat162*)(pKL + off)     = __halves2bfloat162(
                __float2bfloat16(kv.x - __bfloat162float(a0)), __float2bfloat16(kv.y - __bfloat162float(a1)));
            *(__nv_bfloat162*)(pKL + off + 4) = __halves2bfloat162(
                __float2bfloat16(kv.z - __bfloat162float(a2)), __float2bfloat16(kv.w - __bfloat162float(a3)));
            float4 vv = *(const float4*)(vbase + (size_t)r * ATTN_ + c);
            a0 = __float2bfloat16(vv.x); a1 = __float2bfloat16(vv.y);
            a2 = __float2bfloat16(vv.z); a3 = __float2bfloat16(vv.w);
            *(__nv_bfloat162*)(pVH + off)     = __halves2bfloat162(a0, a1);
            *(__nv_bfloat162*)(pVH + off + 4) = __halves2bfloat162(a2, a3);
            *(__nv_bfloat162*)(pVL + off)     = __halves2bfloat162(
                __float2bfloat16(vv.x - __bfloat162float(a0)), __float2bfloat16(vv.y - __bfloat162float(a1)));
            *(__nv_bfloat162*)(pVL + off + 4) = __halves2bfloat162(
                __float2bfloat16(vv.z - __bfloat162float(a2)), __float2bfloat16(vv.w - __bfloat162float(a3)));
        }
        __syncthreads();

        // ---- S = Q K^T (3-term), fp32 acc ----
        float sc[8][4];
#pragma unroll
        for (int nt = 0; nt < 8; nt++)
#pragma unroll
            for (int e = 0; e < 4; e++) sc[nt][e] = 0.f;

#pragma unroll 2
        for (int ks = 0; ks < 8; ks++) {
            const int kc = ks * 16 + lcg;
            uint32_t aQh[4], aQl[4], kh[4][4], kl[4][4];
            ldsm4(aQh, sQH + ((wm + lr) * FLD + kc) * 2);
            ldsm4(aQl, sQL + ((wm + lr) * FLD + kc) * 2);
#pragma unroll
            for (int g = 0; g < 4; g++) {
                ldsm4(kh[g], sKH + ((g * 16 + lr) * FLD + kc) * 2);
                ldsm4(kl[g], sKL + ((g * 16 + lr) * FLD + kc) * 2);
            }
#pragma unroll
            for (int nt = 0; nt < 8; nt++) {
                const uint32_t b0h = kh[nt >> 1][nt & 1], b1h = kh[nt >> 1][(nt & 1) + 2];
                mma16816(sc[nt], aQh, b0h, b1h);
                mma16816(sc[nt], aQh, kl[nt >> 1][nt & 1], kl[nt >> 1][(nt & 1) + 2]);
                mma16816(sc[nt], aQl, b0h, b1h);
            }
        }

        // ---- masking (last two tiles only) + online softmax ----
        if (j >= 2 * qt) {
            const int c0 = j * 64 + ((lane & 3) << 1);
#pragma unroll
            for (int nt = 0; nt < 8; nt++) {
                const int gc = c0 + nt * 8;
                if (gc > grow0)     sc[nt][0] = -1e30f;
                if (gc + 1 > grow0) sc[nt][1] = -1e30f;
                if (gc > grow1)     sc[nt][2] = -1e30f;
                if (gc + 1 > grow1) sc[nt][3] = -1e30f;
            }
        }
        float mx0 = -1e30f, mx1 = -1e30f;
#pragma unroll
        for (int nt = 0; nt < 8; nt++) {
            mx0 = fmaxf(mx0, fmaxf(sc[nt][0], sc[nt][1]));
            mx1 = fmaxf(mx1, fmaxf(sc[nt][2], sc[nt][3]));
        }
        mx0 = fmaxf(mx0, __shfl_xor_sync(0xffffffffu, mx0, 1));
        mx0 = fmaxf(mx0, __shfl_xor_sync(0xffffffffu, mx0, 2));
        mx1 = fmaxf(mx1, __shfl_xor_sync(0xffffffffu, mx1, 1));
        mx1 = fmaxf(mx1, __shfl_xor_sync(0xffffffffu, mx1, 2));
        const float mn0 = fmaxf(m0, mx0), mn1 = fmaxf(m1, mx1);
        const float al0 = __expf(m0 - mn0), al1 = __expf(m1 - mn1);
        float ls0 = 0.f, ls1 = 0.f;
#pragma unroll
        for (int nt = 0; nt < 8; nt++) {
            sc[nt][0] = __expf(sc[nt][0] - mn0);
            sc[nt][1] = __expf(sc[nt][1] - mn0);
            sc[nt][2] = __expf(sc[nt][2] - mn1);
            sc[nt][3] = __expf(sc[nt][3] - mn1);
            ls0 += sc[nt][0] + sc[nt][1];
            ls1 += sc[nt][2] + sc[nt][3];
        }
        ls0 += __shfl_xor_sync(0xffffffffu, ls0, 1);
        ls0 += __shfl_xor_sync(0xffffffffu, ls0, 2);
        ls1 += __shfl_xor_sync(0xffffffffu, ls1, 1);
        ls1 += __shfl_xor_sync(0xffffffffu, ls1, 2);
        l0 = l0 * al0 + ls0; m0 = mn0;
        l1 = l1 * al1 + ls1; m1 = mn1;
#pragma unroll
        for (int nt = 0; nt < 16; nt++) {
            Oacc[nt][0] *= al0; Oacc[nt][1] *= al0;
            Oacc[nt][2] *= al1; Oacc[nt][3] *= al1;
        }

        // ---- O += P V (3-term). P packed from registers (C->A layout). ----
#pragma unroll
        for (int ks = 0; ks < 4; ks++) {
            uint32_t aPh[4], aPl[4];
            {
                const float p0 = sc[2 * ks][0],     p1 = sc[2 * ks][1];
                const float p2 = sc[2 * ks][2],     p3 = sc[2 * ks][3];
                const float p4 = sc[2 * ks + 1][0], p5 = sc[2 * ks + 1][1];
                const float p6 = sc[2 * ks + 1][2], p7 = sc[2 * ks + 1][3];
                aPh[0] = packbf2(p0, p1);
                aPh[1] = packbf2(p2, p3);
                aPh[2] = packbf2(p4, p5);
                aPh[3] = packbf2(p6, p7);
                aPl[0] = packbf2(p0 - __bfloat162float(__float2bfloat16(p0)),
                                 p1 - __bfloat162float(__float2bfloat16(p1)));
                aPl[1] = packbf2(p2 - __bfloat162float(__float2bfloat16(p2)),
                                 p3 - __bfloat162float(__float2bfloat16(p3)));
                aPl[2] = packbf2(p4 - __bfloat162float(__float2bfloat16(p4)),
                                 p5 - __bfloat162float(__float2bfloat16(p5)));
                aPl[3] = packbf2(p6 - __bfloat162float(__float2bfloat16(p6)),
                                 p7 - __bfloat162float(__float2bfloat16(p7)));
            }
#pragma unroll
            for (int ng = 0; ng < 8; ng++) {
                uint32_t bh[4], bl[4];
                const uint32_t va = ((ks * 16 + lr) * FLD + ng * 16 + lcg) * 2;
                ldsm4t(bh, sVH + va);
                ldsm4t(bl, sVL + va);
                mma16816(Oacc[2 * ng], aPh, bh[0], bh[1]);
                mma16816(Oacc[2 * ng], aPh, bl[0], bl[1]);
                mma16816(Oacc[2 * ng], aPl, bh[0], bh[1]);
                mma16816(Oacc[2 * ng + 1], aPh, bh[2], bh[3]);
                mma16816(Oacc[2 * ng + 1], aPh, bl[2], bl[3]);
                mma16816(Oacc[2 * ng + 1], aPl, bh[2], bh[3]);
            }
        }
    }

    // ---- finalize: /l, write fp32 ----
    const float inv0 = 1.0f / l0, inv1 = 1.0f / l1;
    float* ob0 = O + ((size_t)(b * T_) + grow0) * ATTN_ + h * D_;
    float* ob1 = O + ((size_t)(b * T_) + grow1) * ATTN_ + h * D_;
    const int nn = (lane & 3) << 1;
#pragma unroll
    for (int nt = 0; nt < 16; nt++) {
        const int col = nt * 8 + nn;
        *(float2*)(ob0 + col) = make_float2(Oacc[nt][0] * inv0, Oacc[nt][1] * inv0);
        *(float2*)(ob1 + col) = make_float2(Oacc[nt][2] * inv1, Oacc[nt][3] * inv1);
    }
}

// ---------------------------------------------------------------------------
// Host side
// ---------------------------------------------------------------------------
extern "C" void kernel_launch(void* const* d_in, const int* in_sizes, int n_in,
                              void* d_out, int out_size)
{
    const float* x    = (const float*)d_in[0];
    const float* wq_w = (const float*)d_in[3];
    const float* wq_b = (const float*)d_in[4];
    const float* wk_w = (const float*)d_in[5];
    const float* wk_b = (const float*)d_in[6];
    const float* wv_w = (const float*)d_in[7];
    const float* wv_b = (const float*)d_in[8];
    const float* wo_w = (const float*)d_in[9];
    const float* wo_b = (const float*)d_in[10];
    float* out = (float*)d_out;

    float *qp, *kp, *vp, *yp, *cosp, *sinp;
    __nv_bfloat16 *xh, *xl, *yh, *yl, *wh, *wl;
    cudaGetSymbolAddress((void**)&qp, g_q);
    cudaGetSymbolAddress((void**)&kp, g_k);
    cudaGetSymbolAddress((void**)&vp, g_v);
    cudaGetSymbolAddress((void**)&yp, g_y);
    cudaGetSymbolAddress((void**)&cosp, g_cosT);
    cudaGetSymbolAddress((void**)&sinp, g_sinT);
    cudaGetSymbolAddress((void**)&xh, g_xh);
    cudaGetSymbolAddress((void**)&xl, g_xl);
    cudaGetSymbolAddress((void**)&yh, g_yh);
    cudaGetSymbolAddress((void**)&yl, g_yl);
    cudaGetSymbolAddress((void**)&wh, g_wh);
    cudaGetSymbolAddress((void**)&wl, g_wl);

    const size_t WSZ = (size_t)ATTN_ * ATTN_;
    __nv_bfloat16* whp[4] = {wh, wh + WSZ, wh + 2 * WSZ, wh + 3 * WSZ};
    __nv_bfloat16* wlp[4] = {wl, wl + WSZ, wl + 2 * WSZ, wl + 3 * WSZ};

    rope_table_kernel<<<T_, 64>>>(cosp, sinp);
    const int n4x = BT_ * ATTN_ / 4;
    const int n4w = ATTN_ * ATTN_ / 4;
    split_kernel<<<n4x / 256, 256>>>((const float4*)x, (__nv_bfloat162*)xh,
                                     (__nv_bfloat162*)xl, n4x);
    const float* wsrc[4] = {wq_w, wk_w, wv_w, wo_w};
    for (int i = 0; i < 4; i++)
        split_kernel<<<n4w / 256, 256>>>((const float4*)wsrc[i],
                                         (__nv_bfloat162*)whp[i],
                                         (__nv_bfloat162*)wlp[i], n4w);

    cudaFuncSetAttribute(mma_gemm<true>,  cudaFuncAttributeMaxDynamicSharedMemorySize, GEMM_SMEM);
    cudaFuncSetAttribute(mma_gemm<false>, cudaFuncAttributeMaxDynamicSharedMemorySize, GEMM_SMEM);

    dim3 gg(ATTN_ / GBN, BT_ / GBM);
    mma_gemm<true ><<<gg, 256, GEMM_SMEM>>>(xh, xl, whp[0], wlp[0], wq_b, qp, cosp, sinp);
    mma_gemm<true ><<<gg, 256, GEMM_SMEM>>>(xh, xl, whp[1], wlp[1], wk_b, kp, cosp, sinp);
    mma_gemm<false><<<gg, 256, GEMM_SMEM>>>(xh, xl, whp[2], wlp[2], wv_b, vp, cosp, sinp);

    cudaFuncSetAttribute(flash_mma, cudaFuncAttributeMaxDynamicSharedMemorySize, FL2_SMEM);
    flash_mma<<<dim3(T_ / 128, H_, B_), 256, FL2_SMEM>>>(qp, kp, vp, yp);

    split_kernel<<<n4x / 256, 256>>>((const float4*)yp, (__nv_bfloat162*)yh,
                                     (__nv_bfloat162*)yl, n4x);
    mma_gemm<false><<<gg, 256, GEMM_SMEM>>>(yh, yl, whp[3], wlp[3], wo_b, out, cosp, sinp);
}

// round 5
// speedup vs baseline: 2.9218x; 1.0004x over previous
#include <cuda_runtime.h>
#include <cuda_bf16.h>
#include <math.h>
#include <stdint.h>

#define B_    4
#define T_    2048
#define H_    16
#define D_    128
#define ATTN_ 2048
#define BT_   (B_*T_)

// ---------------------------------------------------------------------------
// Scratch (__device__ globals; no allocation allowed). All activations bf16 hi/lo.
// ---------------------------------------------------------------------------
__device__ __nv_bfloat16 g_xh[(size_t)BT_ * ATTN_];
__device__ __nv_bfloat16 g_xl[(size_t)BT_ * ATTN_];
__device__ __nv_bfloat16 g_qh[(size_t)BT_ * ATTN_];
__device__ __nv_bfloat16 g_ql[(size_t)BT_ * ATTN_];
__device__ __nv_bfloat16 g_kh[(size_t)BT_ * ATTN_];
__device__ __nv_bfloat16 g_kl[(size_t)BT_ * ATTN_];
__device__ __nv_bfloat16 g_vh[(size_t)BT_ * ATTN_];
__device__ __nv_bfloat16 g_vl[(size_t)BT_ * ATTN_];
__device__ __nv_bfloat16 g_yh[(size_t)BT_ * ATTN_];
__device__ __nv_bfloat16 g_yl[(size_t)BT_ * ATTN_];
__device__ __nv_bfloat16 g_wh[(size_t)4 * ATTN_ * ATTN_];
__device__ __nv_bfloat16 g_wl[(size_t)4 * ATTN_ * ATTN_];
__device__ float g_cosT[T_ * 64];
__device__ float g_sinT[T_ * 64];

// ---------------------------------------------------------------------------
// PTX helpers (baseline sm_80-era PTX only — sm_103 target has no tcgen05)
// ---------------------------------------------------------------------------
__device__ __forceinline__ uint32_t smem_u32(const void* p) {
    uint32_t a;
    asm("{ .reg .u64 t; cvta.to.shared.u64 t, %1; cvt.u32.u64 %0, t; }" : "=r"(a) : "l"(p));
    return a;
}

#define CP_ASYNC16(dst, src) \
    asm volatile("cp.async.cg.shared.global [%0], [%1], 16;" :: "r"(dst), "l"(src))
#define CP_COMMIT() asm volatile("cp.async.commit_group;" ::: "memory")
#define CP_WAIT(n)  asm volatile("cp.async.wait_group %0;" :: "n"(n) : "memory")

__device__ __forceinline__ void ldsm4(uint32_t* r, uint32_t addr) {
    asm volatile("ldmatrix.sync.aligned.m8n8.x4.shared.b16 {%0,%1,%2,%3}, [%4];"
                 : "=r"(r[0]), "=r"(r[1]), "=r"(r[2]), "=r"(r[3]) : "r"(addr));
}
__device__ __forceinline__ void ldsm4t(uint32_t* r, uint32_t addr) {
    asm volatile("ldmatrix.sync.aligned.m8n8.x4.trans.shared.b16 {%0,%1,%2,%3}, [%4];"
                 : "=r"(r[0]), "=r"(r[1]), "=r"(r[2]), "=r"(r[3]) : "r"(addr));
}

__device__ __forceinline__ void mma16816(float* c, const uint32_t* a,
                                         uint32_t b0, uint32_t b1) {
    asm volatile(
        "mma.sync.aligned.m16n8k16.row.col.f32.bf16.bf16.f32 "
        "{%0,%1,%2,%3}, {%4,%5,%6,%7}, {%8,%9}, {%0,%1,%2,%3};"
        : "+f"(c[0]), "+f"(c[1]), "+f"(c[2]), "+f"(c[3])
        : "r"(a[0]), "r"(a[1]), "r"(a[2]), "r"(a[3]), "r"(b0), "r"(b1));
}

__device__ __forceinline__ uint32_t packbf2(float a, float b) {
    __nv_bfloat162 t = __halves2bfloat162(__float2bfloat16(a), __float2bfloat16(b));
    return *(uint32_t*)&t;
}

// ---------------------------------------------------------------------------
// Small elementwise kernels
// ---------------------------------------------------------------------------
__global__ void rope_table_kernel(float* __restrict__ cosT, float* __restrict__ sinT) {
    const int t = blockIdx.x;
    const int i = threadIdx.x;
    const float kFreq = 0.07195578415606394f;  // ln(10000)/128
    const float inv = expf((float)(2 * i) * -kFreq);
    const float ang = (float)t * inv;
    float s, c;
    sincosf(ang, &s, &c);
    cosT[t * 64 + i] = c;
    sinT[t * 64 + i] = s;
}

__global__ void split_kernel(const float4* __restrict__ src,
                             __nv_bfloat162* __restrict__ hi,
                             __nv_bfloat162* __restrict__ lo, int n4) {
    int i = blockIdx.x * blockDim.x + threadIdx.x;
    if (i >= n4) return;
    float4 v = src[i];
    __nv_bfloat16 h0 = __float2bfloat16(v.x);
    __nv_bfloat16 h1 = __float2bfloat16(v.y);
    __nv_bfloat16 h2 = __float2bfloat16(v.z);
    __nv_bfloat16 h3 = __float2bfloat16(v.w);
    hi[2 * i]     = __halves2bfloat162(h0, h1);
    hi[2 * i + 1] = __halves2bfloat162(h2, h3);
    lo[2 * i]     = __halves2bfloat162(__float2bfloat16(v.x - __bfloat162float(h0)),
                                       __float2bfloat16(v.y - __bfloat162float(h1)));
    lo[2 * i + 1] = __halves2bfloat162(__float2bfloat16(v.z - __bfloat162float(h2)),
                                       __float2bfloat16(v.w - __bfloat162float(h3)));
}

// ---------------------------------------------------------------------------
// bf16x3 GEMM v2: CTA 128x256, warp tile 64x64 (8 warps, 2x4), BK=64.
// C = (Ah+Al)(Wh+Wl)^T + bias, with optional RoPE / scale / bf16-split output.
// ---------------------------------------------------------------------------
static constexpr int GBM = 128, GBN = 256, GBK = 64;
static constexpr int LDS_ = 72;                  // padded row pitch, elems
static constexpr int A_B  = 128 * LDS_ * 2;      // 18432
static constexpr int W_B  = 256 * LDS_ * 2;      // 36864
static constexpr int STAGE_B = 2 * A_B + 2 * W_B;   // 110592
static constexpr int GEMM_SMEM = 2 * STAGE_B;       // 221184

template <bool ROPE, bool SPLIT, bool SCALE>
__global__ void __launch_bounds__(256, 1) mma_gemm(
    const __nv_bfloat16* __restrict__ Ah, const __nv_bfloat16* __restrict__ Al,
    const __nv_bfloat16* __restrict__ Wh, const __nv_bfloat16* __restrict__ Wl,
    const float* __restrict__ bias,
    float* __restrict__ Cf, __nv_bfloat16* __restrict__ CH, __nv_bfloat16* __restrict__ CL,
    const float* __restrict__ cosT, const float* __restrict__ sinT)
{
    extern __shared__ char dsm[];
    const uint32_t sBase = smem_u32(dsm);

    const int tid  = threadIdx.x;
    const int wid  = tid >> 5;
    const int lane = tid & 31;
    const int wm   = (wid >> 2) * 64;   // warp M offset (2 rows of warps)
    const int wn   = (wid & 3) * 64;    // warp N offset (4 cols of warps)
    const int bm   = blockIdx.y * GBM;
    const int bn   = blockIdx.x * GBN;

    const int cc    = tid & 7;          // 16B chunk within 128B row
    const int rbase = tid >> 3;         // 0..31

    const __nv_bfloat16* gAh = Ah + (size_t)bm * ATTN_;
    const __nv_bfloat16* gAl = Al + (size_t)bm * ATTN_;
    const __nv_bfloat16* gWh = Wh + (size_t)bn * ATTN_;
    const __nv_bfloat16* gWl = Wl + (size_t)bn * ATTN_;

    float acc[4][8][4];
#pragma unroll
    for (int mt = 0; mt < 4; mt++)
#pragma unroll
        for (int nt = 0; nt < 8; nt++)
#pragma unroll
            for (int e = 0; e < 4; e++) acc[mt][nt][e] = 0.f;

    const int lr = lane & 15;
    const int lc = (lane >> 4) << 3;
    const int NIT = ATTN_ / GBK;        // 32

    // ---- loader helper (24 cp.async / thread / stage) ----
    auto load_stage = [&](uint32_t st, int k0) {
#pragma unroll
        for (int bb = 0; bb < 4; bb++) {
            const int r = bb * 32 + rbase;
            const uint32_t so = r * (LDS_ * 2) + cc * 16;
            const size_t go = (size_t)r * ATTN_ + k0 + cc * 8;
            CP_ASYNC16(st + so, gAh + go);
            CP_ASYNC16(st + A_B + so, gAl + go);
        }
#pragma unroll
        for (int bb = 0; bb < 8; bb++) {
            const int r = bb * 32 + rbase;
            const uint32_t so = r * (LDS_ * 2) + cc * 16;
            const size_t go = (size_t)r * ATTN_ + k0 + cc * 8;
            CP_ASYNC16(st + 2 * A_B + so, gWh + go);
            CP_ASYNC16(st + 2 * A_B + W_B + so, gWl + go);
        }
        CP_COMMIT();
    };

    load_stage(sBase, 0);

    for (int kt = 0; kt < NIT; kt++) {
        if (kt + 1 < NIT) {
            load_stage(sBase + ((kt + 1) & 1) * STAGE_B, (kt + 1) * GBK);
            CP_WAIT(1);
        } else {
            CP_WAIT(0);
        }
        __syncthreads();

        const uint32_t st  = sBase + (kt & 1) * STAGE_B;
        const uint32_t sAh = st;
        const uint32_t sAl = st + A_B;
        const uint32_t sWh = st + 2 * A_B;
        const uint32_t sWl = st + 2 * A_B + W_B;

#pragma unroll
        for (int ks = 0; ks < 4; ks++) {
            const int kc = ks * 16 + lc;
            uint32_t ah[4][4], whf[4][4], wlf[4][4];
#pragma unroll
            for (int mt = 0; mt < 4; mt++)
                ldsm4(ah[mt], sAh + ((wm + mt * 16 + lr) * LDS_ + kc) * 2);
#pragma unroll
            for (int g = 0; g < 4; g++)
                ldsm4(whf[g], sWh + ((wn + g * 16 + lr) * LDS_ + kc) * 2);
#pragma unroll
            for (int g = 0; g < 4; g++)
                ldsm4(wlf[g], sWl + ((wn + g * 16 + lr) * LDS_ + kc) * 2);

            // Ah * Wh
#pragma unroll
            for (int mt = 0; mt < 4; mt++)
#pragma unroll
                for (int nt = 0; nt < 8; nt++)
                    mma16816(acc[mt][nt], ah[mt], whf[nt >> 1][nt & 1], whf[nt >> 1][(nt & 1) + 2]);
            // Ah * Wl
#pragma unroll
            for (int mt = 0; mt < 4; mt++)
#pragma unroll
                for (int nt = 0; nt < 8; nt++)
                    mma16816(acc[mt][nt], ah[mt], wlf[nt >> 1][nt & 1], wlf[nt >> 1][(nt & 1) + 2]);
            // Al * Wh (reuse ah regs)
#pragma unroll
            for (int mt = 0; mt < 4; mt++)
                ldsm4(ah[mt], sAl + ((wm + mt * 16 + lr) * LDS_ + kc) * 2);
#pragma unroll
            for (int mt = 0; mt < 4; mt++)
#pragma unroll
                for (int nt = 0; nt < 8; nt++)
                    mma16816(acc[mt][nt], ah[mt], whf[nt >> 1][nt & 1], whf[nt >> 1][(nt & 1) + 2]);
        }
        __syncthreads();
    }

    // ---- epilogue: bias (+RoPE) (+scale), fp32 or bf16 hi/lo split output ----
    const int rr = lane >> 2;
    const int nn = (lane & 3) * 2;
    const float qscale = 0.08838834764831843f;   // 1/sqrt(128)
#pragma unroll
    for (int mt = 0; mt < 4; mt++) {
#pragma unroll
        for (int half = 0; half < 2; half++) {
            const int m = bm + wm + mt * 16 + rr + half * 8;
            const int pos = m & (T_ - 1);
#pragma unroll
            for (int nt = 0; nt < 8; nt++) {
                const int n0 = bn + wn + nt * 8 + nn;
                float v0 = acc[mt][nt][half * 2 + 0] + __ldg(&bias[n0]);
                float v1 = acc[mt][nt][half * 2 + 1] + __ldg(&bias[n0 + 1]);
                if (ROPE) {
                    const int pi = (n0 & (D_ - 1)) >> 1;
                    const float cv = __ldg(&cosT[pos * 64 + pi]);
                    const float sv = __ldg(&sinT[pos * 64 + pi]);
                    const float t1 = v0, t2 = v1;
                    v0 = t1 * cv - t2 * sv;
                    v1 = t1 * sv + t2 * cv;
                }
                if (SCALE) { v0 *= qscale; v1 *= qscale; }
                if (SPLIT) {
                    const __nv_bfloat16 h0 = __float2bfloat16(v0);
                    const __nv_bfloat16 h1 = __float2bfloat16(v1);
                    *(__nv_bfloat162*)(CH + (size_t)m * ATTN_ + n0) = __halves2bfloat162(h0, h1);
                    *(__nv_bfloat162*)(CL + (size_t)m * ATTN_ + n0) = __halves2bfloat162(
                        __float2bfloat16(v0 - __bfloat162float(h0)),
                        __float2bfloat16(v1 - __bfloat162float(h1)));
                } else {
                    *(float2*)(Cf + (size_t)m * ATTN_ + n0) = make_float2(v0, v1);
                }
            }
        }
    }
}

// ---------------------------------------------------------------------------
// Tensor-core causal flash attention v2: bf16 hi/lo inputs via cp.async,
// double-buffered KV stages, bf16 hi/lo split output. Q pre-scaled by 1/sqrt(D).
// CTA: 128 q-rows x D=128, 8 warps x 16 rows. KV tiles of 64.
// ---------------------------------------------------------------------------
static constexpr int FLD = 136;
static constexpr int FQB = 128 * FLD * 2;   // 34816
static constexpr int FKB = 64 * FLD * 2;    // 17408
static constexpr int FSTG = 4 * FKB;        // 69632
static constexpr int FSMEM = 2 * FQB + 2 * FSTG;  // 208896

__global__ void __launch_bounds__(256, 1) flash_mma(
    const __nv_bfloat16* __restrict__ Qh, const __nv_bfloat16* __restrict__ Ql,
    const __nv_bfloat16* __restrict__ Kh, const __nv_bfloat16* __restrict__ Kl,
    const __nv_bfloat16* __restrict__ Vh, const __nv_bfloat16* __restrict__ Vl,
    __nv_bfloat16* __restrict__ Yh, __nv_bfloat16* __restrict__ Yl)
{
    extern __shared__ char fsm[];
    const uint32_t sb  = smem_u32(fsm);
    const uint32_t sQH = sb;
    const uint32_t sQL = sb + FQB;
    const uint32_t sKV = sb + 2 * FQB;

    const int qt = blockIdx.x, h = blockIdx.y, b = blockIdx.z;
    const int tid = threadIdx.x, wid = tid >> 5, lane = tid & 31;
    const int wm = wid * 16;
    const int lr = lane & 15;
    const int lcg = (lane >> 4) << 3;

    const int ccf = tid & 15;     // 16B chunk within 256B row
    const int r0f = tid >> 4;     // 0..15

    // ---- Q load (one group) ----
    {
        const __nv_bfloat16* qh_g = Qh + ((size_t)(b * T_ + qt * 128)) * ATTN_ + h * D_;
        const __nv_bfloat16* ql_g = Ql + ((size_t)(b * T_ + qt * 128)) * ATTN_ + h * D_;
#pragma unroll
        for (int bb = 0; bb < 8; bb++) {
            const int r = bb * 16 + r0f;
            const uint32_t so = r * (FLD * 2) + ccf * 16;
            const size_t go = (size_t)r * ATTN_ + ccf * 8;
            CP_ASYNC16(sQH + so, qh_g + go);
            CP_ASYNC16(sQL + so, ql_g + go);
        }
        CP_COMMIT();
    }

    const int nkv = 2 * qt + 2;

    auto issue_kv = [&](int j) {
        const uint32_t st = sKV + (j & 1) * FSTG;
        const size_t base = ((size_t)(b * T_ + j * 64)) * ATTN_ + h * D_;
#pragma unroll
        for (int bb = 0; bb < 4; bb++) {
            const int r = bb * 16 + r0f;
            const uint32_t so = r * (FLD * 2) + ccf * 16;
            const size_t go = base + (size_t)r * ATTN_ + ccf * 8;
            CP_ASYNC16(st + so, Kh + go);
            CP_ASYNC16(st + FKB + so, Kl + go);
            CP_ASYNC16(st + 2 * FKB + so, Vh + go);
            CP_ASYNC16(st + 3 * FKB + so, Vl + go);
        }
        CP_COMMIT();
    };

    issue_kv(0);

    float Oacc[16][4];
#pragma unroll
    for (int nt = 0; nt < 16; nt++)
#pragma unroll
        for (int e = 0; e < 4; e++) Oacc[nt][e] = 0.f;
    float m0 = -1e30f, m1 = -1e30f, l0 = 0.f, l1 = 0.f;

    const int grow0 = qt * 128 + wm + (lane >> 2);
    const int grow1 = grow0 + 8;

    for (int j = 0; j < nkv; j++) {
        if (j + 1 < nkv) {
            issue_kv(j + 1);
            CP_WAIT(1);
        } else {
            CP_WAIT(0);
        }
        __syncthreads();

        const uint32_t st  = sKV + (j & 1) * FSTG;
        const uint32_t cKH = st;
        const uint32_t cKL = st + FKB;
        const uint32_t cVH = st + 2 * FKB;
        const uint32_t cVL = st + 3 * FKB;

        // ---- S = Q K^T (3-term), fp32 acc ----
        float sc[8][4];
#pragma unroll
        for (int nt = 0; nt < 8; nt++)
#pragma unroll
            for (int e = 0; e < 4; e++) sc[nt][e] = 0.f;

#pragma unroll 2
        for (int ks = 0; ks < 8; ks++) {
            const int kc = ks * 16 + lcg;
            uint32_t aQh[4], aQl[4], kh[4][4], kl[4][4];
            ldsm4(aQh, sQH + ((wm + lr) * FLD + kc) * 2);
            ldsm4(aQl, sQL + ((wm + lr) * FLD + kc) * 2);
#pragma unroll
            for (int g = 0; g < 4; g++) {
                ldsm4(kh[g], cKH + ((g * 16 + lr) * FLD + kc) * 2);
                ldsm4(kl[g], cKL + ((g * 16 + lr) * FLD + kc) * 2);
            }
#pragma unroll
            for (int nt = 0; nt < 8; nt++) {
                const uint32_t b0h = kh[nt >> 1][nt & 1], b1h = kh[nt >> 1][(nt & 1) + 2];
                mma16816(sc[nt], aQh, b0h, b1h);
                mma16816(sc[nt], aQh, kl[nt >> 1][nt & 1], kl[nt >> 1][(nt & 1) + 2]);
                mma16816(sc[nt], aQl, b0h, b1h);
            }
        }

        // ---- masking (last two tiles) + online softmax ----
        if (j >= 2 * qt) {
            const int c0 = j * 64 + ((lane & 3) << 1);
#pragma unroll
            for (int nt = 0; nt < 8; nt++) {
                const int gc = c0 + nt * 8;
                if (gc > grow0)     sc[nt][0] = -1e30f;
                if (gc + 1 > grow0) sc[nt][1] = -1e30f;
                if (gc > grow1)     sc[nt][2] = -1e30f;
                if (gc + 1 > grow1) sc[nt][3] = -1e30f;
            }
        }
        float mx0 = -1e30f, mx1 = -1e30f;
#pragma unroll
        for (int nt = 0; nt < 8; nt++) {
            mx0 = fmaxf(mx0, fmaxf(sc[nt][0], sc[nt][1]));
            mx1 = fmaxf(mx1, fmaxf(sc[nt][2], sc[nt][3]));
        }
        mx0 = fmaxf(mx0, __shfl_xor_sync(0xffffffffu, mx0, 1));
        mx0 = fmaxf(mx0, __shfl_xor_sync(0xffffffffu, mx0, 2));
        mx1 = fmaxf(mx1, __shfl_xor_sync(0xffffffffu, mx1, 1));
        mx1 = fmaxf(mx1, __shfl_xor_sync(0xffffffffu, mx1, 2));
        const float mn0 = fmaxf(m0, mx0), mn1 = fmaxf(m1, mx1);
        const float al0 = __expf(m0 - mn0), al1 = __expf(m1 - mn1);
        float ls0 = 0.f, ls1 = 0.f;
#pragma unroll
        for (int nt = 0; nt < 8; nt++) {
            sc[nt][0] = __expf(sc[nt][0] - mn0);
            sc[nt][1] = __expf(sc[nt][1] - mn0);
            sc[nt][2] = __expf(sc[nt][2] - mn1);
            sc[nt][3] = __expf(sc[nt][3] - mn1);
            ls0 += sc[nt][0] + sc[nt][1];
            ls1 += sc[nt][2] + sc[nt][3];
        }
        ls0 += __shfl_xor_sync(0xffffffffu, ls0, 1);
        ls0 += __shfl_xor_sync(0xffffffffu, ls0, 2);
        ls1 += __shfl_xor_sync(0xffffffffu, ls1, 1);
        ls1 += __shfl_xor_sync(0xffffffffu, ls1, 2);
        l0 = l0 * al0 + ls0; m0 = mn0;
        l1 = l1 * al1 + ls1; m1 = mn1;
#pragma unroll
        for (int nt = 0; nt < 16; nt++) {
            Oacc[nt][0] *= al0; Oacc[nt][1] *= al0;
            Oacc[nt][2] *= al1; Oacc[nt][3] *= al1;
        }

        // ---- O += P V (3-term) ----
#pragma unroll
        for (int ks = 0; ks < 4; ks++) {
            uint32_t aPh[4], aPl[4];
            {
                const float p0 = sc[2 * ks][0],     p1 = sc[2 * ks][1];
                const float p2 = sc[2 * ks][2],     p3 = sc[2 * ks][3];
                const float p4 = sc[2 * ks + 1][0], p5 = sc[2 * ks + 1][1];
                const float p6 = sc[2 * ks + 1][2], p7 = sc[2 * ks + 1][3];
                aPh[0] = packbf2(p0, p1);
                aPh[1] = packbf2(p2, p3);
                aPh[2] = packbf2(p4, p5);
                aPh[3] = packbf2(p6, p7);
                aPl[0] = packbf2(p0 - __bfloat162float(__float2bfloat16(p0)),
                                 p1 - __bfloat162float(__float2bfloat16(p1)));
                aPl[1] = packbf2(p2 - __bfloat162float(__float2bfloat16(p2)),
                                 p3 - __bfloat162float(__float2bfloat16(p3)));
                aPl[2] = packbf2(p4 - __bfloat162float(__float2bfloat16(p4)),
                                 p5 - __bfloat162float(__float2bfloat16(p5)));
                aPl[3] = packbf2(p6 - __bfloat162float(__float2bfloat16(p6)),
                                 p7 - __bfloat162float(__float2bfloat16(p7)));
            }
#pragma unroll
            for (int ng = 0; ng < 8; ng++) {
                uint32_t bh[4], bl[4];
                const uint32_t va = ((ks * 16 + lr) * FLD + ng * 16 + lcg) * 2;
                ldsm4t(bh, cVH + va);
                ldsm4t(bl, cVL + va);
                mma16816(Oacc[2 * ng], aPh, bh[0], bh[1]);
                mma16816(Oacc[2 * ng], aPh, bl[0], bl[1]);
                mma16816(Oacc[2 * ng], aPl, bh[0], bh[1]);
                mma16816(Oacc[2 * ng + 1], aPh, bh[2], bh[3]);
                mma16816(Oacc[2 * ng + 1], aPh, bl[2], bl[3]);
                mma16816(Oacc[2 * ng + 1], aPl, bh[2], bh[3]);
            }
        }
        __syncthreads();
    }

    // ---- finalize: /l, split hi/lo, store bf16 ----
    const float inv0 = 1.0f / l0, inv1 = 1.0f / l1;
    const size_t rb0 = ((size_t)(b * T_) + grow0) * ATTN_ + h * D_;
    const size_t rb1 = ((size_t)(b * T_) + grow1) * ATTN_ + h * D_;
    const int nn = (lane & 3) << 1;
#pragma unroll
    for (int nt = 0; nt < 16; nt++) {
        const int col = nt * 8 + nn;
        {
            const float v0 = Oacc[nt][0] * inv0, v1 = Oacc[nt][1] * inv0;
            const __nv_bfloat16 h0 = __float2bfloat16(v0), h1 = __float2bfloat16(v1);
            *(__nv_bfloat162*)(Yh + rb0 + col) = __halves2bfloat162(h0, h1);
            *(__nv_bfloat162*)(Yl + rb0 + col) = __halves2bfloat162(
                __float2bfloat16(v0 - __bfloat162float(h0)),
                __float2bfloat16(v1 - __bfloat162float(h1)));
        }
        {
            const float v0 = Oacc[nt][2] * inv1, v1 = Oacc[nt][3] * inv1;
            const __nv_bfloat16 h0 = __float2bfloat16(v0), h1 = __float2bfloat16(v1);
            *(__nv_bfloat162*)(Yh + rb1 + col) = __halves2bfloat162(h0, h1);
            *(__nv_bfloat162*)(Yl + rb1 + col) = __halves2bfloat162(
                __float2bfloat16(v0 - __bfloat162float(h0)),
                __float2bfloat16(v1 - __bfloat162float(h1)));
        }
    }
}

// ---------------------------------------------------------------------------
// Host side
// ---------------------------------------------------------------------------
extern "C" void kernel_launch(void* const* d_in, const int* in_sizes, int n_in,
                              void* d_out, int out_size)
{
    const float* x    = (const float*)d_in[0];
    const float* wq_w = (const float*)d_in[3];
    const float* wq_b = (const float*)d_in[4];
    const float* wk_w = (const float*)d_in[5];
    const float* wk_b = (const float*)d_in[6];
    const float* wv_w = (const float*)d_in[7];
    const float* wv_b = (const float*)d_in[8];
    const float* wo_w = (const float*)d_in[9];
    const float* wo_b = (const float*)d_in[10];
    float* out = (float*)d_out;

    float *cosp, *sinp;
    __nv_bfloat16 *xh, *xl, *qh, *ql, *kh, *kl, *vh, *vl, *yh, *yl, *wh, *wl;
    cudaGetSymbolAddress((void**)&cosp, g_cosT);
    cudaGetSymbolAddress((void**)&sinp, g_sinT);
    cudaGetSymbolAddress((void**)&xh, g_xh);
    cudaGetSymbolAddress((void**)&xl, g_xl);
    cudaGetSymbolAddress((void**)&qh, g_qh);
    cudaGetSymbolAddress((void**)&ql, g_ql);
    cudaGetSymbolAddress((void**)&kh, g_kh);
    cudaGetSymbolAddress((void**)&kl, g_kl);
    cudaGetSymbolAddress((void**)&vh, g_vh);
    cudaGetSymbolAddress((void**)&vl, g_vl);
    cudaGetSymbolAddress((void**)&yh, g_yh);
    cudaGetSymbolAddress((void**)&yl, g_yl);
    cudaGetSymbolAddress((void**)&wh, g_wh);
    cudaGetSymbolAddress((void**)&wl, g_wl);

    const size_t WSZ = (size_t)ATTN_ * ATTN_;
    __nv_bfloat16* whp[4] = {wh, wh + WSZ, wh + 2 * WSZ, wh + 3 * WSZ};
    __nv_bfloat16* wlp[4] = {wl, wl + WSZ, wl + 2 * WSZ, wl + 3 * WSZ};

    rope_table_kernel<<<T_, 64>>>(cosp, sinp);
    const int n4x = BT_ * ATTN_ / 4;
    const int n4w = ATTN_ * ATTN_ / 4;
    split_kernel<<<n4x / 256, 256>>>((const float4*)x, (__nv_bfloat162*)xh,
                                     (__nv_bfloat162*)xl, n4x);
    const float* wsrc[4] = {wq_w, wk_w, wv_w, wo_w};
    for (int i = 0; i < 4; i++)
        split_kernel<<<n4w / 256, 256>>>((const float4*)wsrc[i],
                                         (__nv_bfloat162*)whp[i],
                                         (__nv_bfloat162*)wlp[i], n4w);

    cudaFuncSetAttribute(mma_gemm<true,  true,  true >, cudaFuncAttributeMaxDynamicSharedMemorySize, GEMM_SMEM);
    cudaFuncSetAttribute(mma_gemm<true,  true,  false>, cudaFuncAttributeMaxDynamicSharedMemorySize, GEMM_SMEM);
    cudaFuncSetAttribute(mma_gemm<false, true,  false>, cudaFuncAttributeMaxDynamicSharedMemorySize, GEMM_SMEM);
    cudaFuncSetAttribute(mma_gemm<false, false, false>, cudaFuncAttributeMaxDynamicSharedMemorySize, GEMM_SMEM);

    dim3 gg(ATTN_ / GBN, BT_ / GBM);   // (8, 64)
    mma_gemm<true,  true,  true ><<<gg, 256, GEMM_SMEM>>>(xh, xl, whp[0], wlp[0], wq_b,
                                                          nullptr, qh, ql, cosp, sinp);
    mma_gemm<true,  true,  false><<<gg, 256, GEMM_SMEM>>>(xh, xl, whp[1], wlp[1], wk_b,
                                                          nullptr, kh, kl, cosp, sinp);
    mma_gemm<false, true,  false><<<gg, 256, GEMM_SMEM>>>(xh, xl, whp[2], wlp[2], wv_b,
                                                          nullptr, vh, vl, cosp, sinp);

    cudaFuncSetAttribute(flash_mma, cudaFuncAttributeMaxDynamicSharedMemorySize, FSMEM);
    flash_mma<<<dim3(T_ / 128, H_, B_), 256, FSMEM>>>(qh, ql, kh, kl, vh, vl, yh, yl);

    mma_gemm<false, false, false><<<gg, 256, GEMM_SMEM>>>(yh, yl, whp[3], wlp[3], wo_b,
                                                          out, nullptr, nullptr, cosp, sinp);
}

// round 6
// speedup vs baseline: 3.1086x; 1.0639x over previous
#include <cuda_runtime.h>
#include <cuda_bf16.h>
#include <math.h>
#include <stdint.h>

#define B_    4
#define T_    2048
#define H_    16
#define D_    128
#define ATTN_ 2048
#define BT_   (B_*T_)

// ---------------------------------------------------------------------------
// Scratch (__device__ globals). Weights concat: rows 0-6143 = wq|wk|wv, 6144+ = wo.
// ---------------------------------------------------------------------------
__device__ __nv_bfloat16 g_xh[(size_t)BT_ * ATTN_];
__device__ __nv_bfloat16 g_xl[(size_t)BT_ * ATTN_];
__device__ __nv_bfloat16 g_qh[(size_t)BT_ * ATTN_];
__device__ __nv_bfloat16 g_ql[(size_t)BT_ * ATTN_];
__device__ __nv_bfloat16 g_kh[(size_t)BT_ * ATTN_];
__device__ __nv_bfloat16 g_kl[(size_t)BT_ * ATTN_];
__device__ __nv_bfloat16 g_vh[(size_t)BT_ * ATTN_];
__device__ __nv_bfloat16 g_vl[(size_t)BT_ * ATTN_];
__device__ __nv_bfloat16 g_yh[(size_t)BT_ * ATTN_];
__device__ __nv_bfloat16 g_yl[(size_t)BT_ * ATTN_];
__device__ __nv_bfloat16 g_wh[(size_t)4 * ATTN_ * ATTN_];
__device__ __nv_bfloat16 g_wl[(size_t)4 * ATTN_ * ATTN_];
__device__ float g_cosT[T_ * 64];
__device__ float g_sinT[T_ * 64];

// ---------------------------------------------------------------------------
// PTX helpers
// ---------------------------------------------------------------------------
__device__ __forceinline__ uint32_t smem_u32(const void* p) {
    uint32_t a;
    asm("{ .reg .u64 t; cvta.to.shared.u64 t, %1; cvt.u32.u64 %0, t; }" : "=r"(a) : "l"(p));
    return a;
}

#define CP_ASYNC16(dst, src) \
    asm volatile("cp.async.cg.shared.global [%0], [%1], 16;" :: "r"(dst), "l"(src))
#define CP_COMMIT() asm volatile("cp.async.commit_group;" ::: "memory")
#define CP_WAIT(n)  asm volatile("cp.async.wait_group %0;" :: "n"(n) : "memory")

__device__ __forceinline__ void ldsm4(uint32_t* r, uint32_t addr) {
    asm volatile("ldmatrix.sync.aligned.m8n8.x4.shared.b16 {%0,%1,%2,%3}, [%4];"
                 : "=r"(r[0]), "=r"(r[1]), "=r"(r[2]), "=r"(r[3]) : "r"(addr));
}
__device__ __forceinline__ void ldsm4t(uint32_t* r, uint32_t addr) {
    asm volatile("ldmatrix.sync.aligned.m8n8.x4.trans.shared.b16 {%0,%1,%2,%3}, [%4];"
                 : "=r"(r[0]), "=r"(r[1]), "=r"(r[2]), "=r"(r[3]) : "r"(addr));
}

__device__ __forceinline__ void mma16816(float* c, const uint32_t* a,
                                         uint32_t b0, uint32_t b1) {
    asm volatile(
        "mma.sync.aligned.m16n8k16.row.col.f32.bf16.bf16.f32 "
        "{%0,%1,%2,%3}, {%4,%5,%6,%7}, {%8,%9}, {%0,%1,%2,%3};"
        : "+f"(c[0]), "+f"(c[1]), "+f"(c[2]), "+f"(c[3])
        : "r"(a[0]), "r"(a[1]), "r"(a[2]), "r"(a[3]), "r"(b0), "r"(b1));
}

__device__ __forceinline__ uint32_t packbf2(float a, float b) {
    __nv_bfloat162 t = __halves2bfloat162(__float2bfloat16(a), __float2bfloat16(b));
    return *(uint32_t*)&t;
}

// ---------------------------------------------------------------------------
// Elementwise kernels
// ---------------------------------------------------------------------------
__global__ void rope_table_kernel(float* __restrict__ cosT, float* __restrict__ sinT) {
    const int t = blockIdx.x;
    const int i = threadIdx.x;
    const float kFreq = 0.07195578415606394f;  // ln(10000)/128
    const float inv = expf((float)(2 * i) * -kFreq);
    const float ang = (float)t * inv;
    float s, c;
    sincosf(ang, &s, &c);
    cosT[t * 64 + i] = c;
    sinT[t * 64 + i] = s;
}

__global__ void split_kernel(const float4* __restrict__ src,
                             __nv_bfloat162* __restrict__ hi,
                             __nv_bfloat162* __restrict__ lo, int n4) {
    int i = blockIdx.x * blockDim.x + threadIdx.x;
    if (i >= n4) return;
    float4 v = src[i];
    __nv_bfloat16 h0 = __float2bfloat16(v.x);
    __nv_bfloat16 h1 = __float2bfloat16(v.y);
    __nv_bfloat16 h2 = __float2bfloat16(v.z);
    __nv_bfloat16 h3 = __float2bfloat16(v.w);
    hi[2 * i]     = __halves2bfloat162(h0, h1);
    hi[2 * i + 1] = __halves2bfloat162(h2, h3);
    lo[2 * i]     = __halves2bfloat162(__float2bfloat16(v.x - __bfloat162float(h0)),
                                       __float2bfloat16(v.y - __bfloat162float(h1)));
    lo[2 * i + 1] = __halves2bfloat162(__float2bfloat16(v.z - __bfloat162float(h2)),
                                       __float2bfloat16(v.w - __bfloat162float(h3)));
}

// One launch for all 4 weight matrices: grid.z selects source; dest = concat slot z.
__global__ void split_w_kernel(const float* __restrict__ w0, const float* __restrict__ w1,
                               const float* __restrict__ w2, const float* __restrict__ w3,
                               __nv_bfloat162* __restrict__ hi, __nv_bfloat162* __restrict__ lo,
                               int n4) {
    int i = blockIdx.x * blockDim.x + threadIdx.x;
    if (i >= n4) return;
    const int z = blockIdx.z;
    const float* src = (z == 0) ? w0 : (z == 1) ? w1 : (z == 2) ? w2 : w3;
    float4 v = ((const float4*)src)[i];
    const size_t off = (size_t)z * n4 * 2;   // n4*2 bfloat162 per matrix
    __nv_bfloat16 h0 = __float2bfloat16(v.x);
    __nv_bfloat16 h1 = __float2bfloat16(v.y);
    __nv_bfloat16 h2 = __float2bfloat16(v.z);
    __nv_bfloat16 h3 = __float2bfloat16(v.w);
    hi[off + 2 * i]     = __halves2bfloat162(h0, h1);
    hi[off + 2 * i + 1] = __halves2bfloat162(h2, h3);
    lo[off + 2 * i]     = __halves2bfloat162(__float2bfloat16(v.x - __bfloat162float(h0)),
                                             __float2bfloat16(v.y - __bfloat162float(h1)));
    lo[off + 2 * i + 1] = __halves2bfloat162(__float2bfloat16(v.z - __bfloat162float(h2)),
                                             __float2bfloat16(v.w - __bfloat162float(h3)));
}

// ---------------------------------------------------------------------------
// GEMM tiles/layout constants (CTA 128x256, warp 64x64, BK=64, 2-stage)
// ---------------------------------------------------------------------------
static constexpr int GBM = 128, GBN = 256, GBK = 64;
static constexpr int LDS_ = 72;
static constexpr int A_B  = 128 * LDS_ * 2;      // 18432
static constexpr int W_B  = 256 * LDS_ * 2;      // 36864
static constexpr int STAGE_B = 2 * A_B + 2 * W_B;   // 110592
static constexpr int GEMM_SMEM = 2 * STAGE_B;       // 221184

// Shared mainloop. Computes acc for one 128x256 tile.
struct GemmCore {
    __device__ static __forceinline__ void run(
        uint32_t sBase, float (&acc)[4][8][4],
        const __nv_bfloat16* gAh, const __nv_bfloat16* gAl,
        const __nv_bfloat16* gWh, const __nv_bfloat16* gWl,
        int tid, int wm, int wn, int lr, int lc)
    {
        const int cc    = tid & 7;
        const int rbase = tid >> 3;
        const int NIT = ATTN_ / GBK;

        auto load_stage = [&](uint32_t st, int k0) {
#pragma unroll
            for (int bb = 0; bb < 4; bb++) {
                const int r = bb * 32 + rbase;
                const uint32_t so = r * (LDS_ * 2) + cc * 16;
                const size_t go = (size_t)r * ATTN_ + k0 + cc * 8;
                CP_ASYNC16(st + so, gAh + go);
                CP_ASYNC16(st + A_B + so, gAl + go);
            }
#pragma unroll
            for (int bb = 0; bb < 8; bb++) {
                const int r = bb * 32 + rbase;
                const uint32_t so = r * (LDS_ * 2) + cc * 16;
                const size_t go = (size_t)r * ATTN_ + k0 + cc * 8;
                CP_ASYNC16(st + 2 * A_B + so, gWh + go);
                CP_ASYNC16(st + 2 * A_B + W_B + so, gWl + go);
            }
            CP_COMMIT();
        };

        load_stage(sBase, 0);

        for (int kt = 0; kt < NIT; kt++) {
            if (kt + 1 < NIT) {
                load_stage(sBase + ((kt + 1) & 1) * STAGE_B, (kt + 1) * GBK);
                CP_WAIT(1);
            } else {
                CP_WAIT(0);
            }
            __syncthreads();

            const uint32_t st  = sBase + (kt & 1) * STAGE_B;
            const uint32_t sAh = st;
            const uint32_t sAl = st + A_B;
            const uint32_t sWh = st + 2 * A_B;
            const uint32_t sWl = st + 2 * A_B + W_B;

#pragma unroll
            for (int ks = 0; ks < 4; ks++) {
                const int kc = ks * 16 + lc;
                uint32_t ah[4][4], whf[4][4], wlf[4][4];
#pragma unroll
                for (int mt = 0; mt < 4; mt++)
                    ldsm4(ah[mt], sAh + ((wm + mt * 16 + lr) * LDS_ + kc) * 2);
#pragma unroll
                for (int g = 0; g < 4; g++)
                    ldsm4(whf[g], sWh + ((wn + g * 16 + lr) * LDS_ + kc) * 2);
#pragma unroll
                for (int g = 0; g < 4; g++)
                    ldsm4(wlf[g], sWl + ((wn + g * 16 + lr) * LDS_ + kc) * 2);

#pragma unroll
                for (int mt = 0; mt < 4; mt++)
#pragma unroll
                    for (int nt = 0; nt < 8; nt++)
                        mma16816(acc[mt][nt], ah[mt], whf[nt >> 1][nt & 1], whf[nt >> 1][(nt & 1) + 2]);
#pragma unroll
                for (int mt = 0; mt < 4; mt++)
#pragma unroll
                    for (int nt = 0; nt < 8; nt++)
                        mma16816(acc[mt][nt], ah[mt], wlf[nt >> 1][nt & 1], wlf[nt >> 1][(nt & 1) + 2]);
#pragma unroll
                for (int mt = 0; mt < 4; mt++)
                    ldsm4(ah[mt], sAl + ((wm + mt * 16 + lr) * LDS_ + kc) * 2);
#pragma unroll
                for (int mt = 0; mt < 4; mt++)
#pragma unroll
                    for (int nt = 0; nt < 8; nt++)
                        mma16816(acc[mt][nt], ah[mt], whf[nt >> 1][nt & 1], whf[nt >> 1][(nt & 1) + 2]);
            }
            __syncthreads();
        }
    }
};

// ---------------------------------------------------------------------------
// Fused QKV projection GEMM. grid (24, 64). blockIdx.x>>3 : 0=Q,1=K,2=V.
// Weights are the concat matrix (rows 0..6143). Epilogue: bias, RoPE (Q,K),
// 1/sqrt(D) scale (Q), bf16 hi/lo split output.
// ---------------------------------------------------------------------------
__global__ void __launch_bounds__(256, 1) qkv_gemm(
    const __nv_bfloat16* __restrict__ Xh, const __nv_bfloat16* __restrict__ Xl,
    const __nv_bfloat16* __restrict__ Wh, const __nv_bfloat16* __restrict__ Wl,
    const float* __restrict__ bq, const float* __restrict__ bk, const float* __restrict__ bv,
    __nv_bfloat16* __restrict__ QH, __nv_bfloat16* __restrict__ QL,
    __nv_bfloat16* __restrict__ KH, __nv_bfloat16* __restrict__ KL,
    __nv_bfloat16* __restrict__ VH, __nv_bfloat16* __restrict__ VL,
    const float* __restrict__ cosT, const float* __restrict__ sinT)
{
    extern __shared__ char dsm[];
    const uint32_t sBase = smem_u32(dsm);

    const int tid  = threadIdx.x;
    const int wid  = tid >> 5;
    const int lane = tid & 31;
    const int wm   = (wid >> 2) * 64;
    const int wn   = (wid & 3) * 64;
    const int bm   = blockIdx.y * GBM;
    const int qkv  = blockIdx.x >> 3;              // 0,1,2
    const int bnl  = (blockIdx.x & 7) * GBN;       // local N offset within q/k/v
    const int bng  = blockIdx.x * GBN;             // global concat W row

    float acc[4][8][4];
#pragma unroll
    for (int mt = 0; mt < 4; mt++)
#pragma unroll
        for (int nt = 0; nt < 8; nt++)
#pragma unroll
            for (int e = 0; e < 4; e++) acc[mt][nt][e] = 0.f;

    GemmCore::run(sBase, acc,
                  Xh + (size_t)bm * ATTN_, Xl + (size_t)bm * ATTN_,
                  Wh + (size_t)bng * ATTN_, Wl + (size_t)bng * ATTN_,
                  tid, wm, wn, lane & 15, (lane >> 4) << 3);

    const float* bias = (qkv == 0) ? bq : (qkv == 1) ? bk : bv;
    __nv_bfloat16* CH = (qkv == 0) ? QH : (qkv == 1) ? KH : VH;
    __nv_bfloat16* CL = (qkv == 0) ? QL : (qkv == 1) ? KL : VL;
    const bool rope  = (qkv != 2);
    const bool scale = (qkv == 0);
    const float qscale = 0.08838834764831843f;

    const int rr = lane >> 2;
    const int nn = (lane & 3) * 2;
#pragma unroll
    for (int mt = 0; mt < 4; mt++) {
#pragma unroll
        for (int half = 0; half < 2; half++) {
            const int m = bm + wm + mt * 16 + rr + half * 8;
            const int pos = m & (T_ - 1);
#pragma unroll
            for (int nt = 0; nt < 8; nt++) {
                const int n0 = bnl + wn + nt * 8 + nn;
                float v0 = acc[mt][nt][half * 2 + 0] + __ldg(&bias[n0]);
                float v1 = acc[mt][nt][half * 2 + 1] + __ldg(&bias[n0 + 1]);
                if (rope) {
                    const int pi = (n0 & (D_ - 1)) >> 1;
                    const float cv = __ldg(&cosT[pos * 64 + pi]);
                    const float sv = __ldg(&sinT[pos * 64 + pi]);
                    const float t1 = v0, t2 = v1;
                    v0 = t1 * cv - t2 * sv;
                    v1 = t1 * sv + t2 * cv;
                }
                if (scale) { v0 *= qscale; v1 *= qscale; }
                const __nv_bfloat16 h0 = __float2bfloat16(v0);
                const __nv_bfloat16 h1 = __float2bfloat16(v1);
                *(__nv_bfloat162*)(CH + (size_t)m * ATTN_ + n0) = __halves2bfloat162(h0, h1);
                *(__nv_bfloat162*)(CL + (size_t)m * ATTN_ + n0) = __halves2bfloat162(
                    __float2bfloat16(v0 - __bfloat162float(h0)),
                    __float2bfloat16(v1 - __bfloat162float(h1)));
            }
        }
    }
}

// ---------------------------------------------------------------------------
// Output projection GEMM: fp32 out, bias, no RoPE.
// ---------------------------------------------------------------------------
__global__ void __launch_bounds__(256, 1) out_gemm(
    const __nv_bfloat16* __restrict__ Ah, const __nv_bfloat16* __restrict__ Al,
    const __nv_bfloat16* __restrict__ Wh, const __nv_bfloat16* __restrict__ Wl,
    const float* __restrict__ bias, float* __restrict__ Cf)
{
    extern __shared__ char dsm[];
    const uint32_t sBase = smem_u32(dsm);

    const int tid  = threadIdx.x;
    const int wid  = tid >> 5;
    const int lane = tid & 31;
    const int wm   = (wid >> 2) * 64;
    const int wn   = (wid & 3) * 64;
    const int bm   = blockIdx.y * GBM;
    const int bn   = blockIdx.x * GBN;

    float acc[4][8][4];
#pragma unroll
    for (int mt = 0; mt < 4; mt++)
#pragma unroll
        for (int nt = 0; nt < 8; nt++)
#pragma unroll
            for (int e = 0; e < 4; e++) acc[mt][nt][e] = 0.f;

    GemmCore::run(sBase, acc,
                  Ah + (size_t)bm * ATTN_, Al + (size_t)bm * ATTN_,
                  Wh + (size_t)bn * ATTN_, Wl + (size_t)bn * ATTN_,
                  tid, wm, wn, lane & 15, (lane >> 4) << 3);

    const int rr = lane >> 2;
    const int nn = (lane & 3) * 2;
#pragma unroll
    for (int mt = 0; mt < 4; mt++) {
#pragma unroll
        for (int half = 0; half < 2; half++) {
            const int m = bm + wm + mt * 16 + rr + half * 8;
#pragma unroll
            for (int nt = 0; nt < 8; nt++) {
                const int n0 = bn + wn + nt * 8 + nn;
                const float v0 = acc[mt][nt][half * 2 + 0] + __ldg(&bias[n0]);
                const float v1 = acc[mt][nt][half * 2 + 1] + __ldg(&bias[n0 + 1]);
                *(float2*)(Cf + (size_t)m * ATTN_ + n0) = make_float2(v0, v1);
            }
        }
    }
}

// ---------------------------------------------------------------------------
// Tensor-core causal flash attention (unchanged from round 5, passing).
// ---------------------------------------------------------------------------
static constexpr int FLD = 136;
static constexpr int FQB = 128 * FLD * 2;
static constexpr int FKB = 64 * FLD * 2;
static constexpr int FSTG = 4 * FKB;
static constexpr int FSMEM = 2 * FQB + 2 * FSTG;

__global__ void __launch_bounds__(256, 1) flash_mma(
    const __nv_bfloat16* __restrict__ Qh, const __nv_bfloat16* __restrict__ Ql,
    const __nv_bfloat16* __restrict__ Kh, const __nv_bfloat16* __restrict__ Kl,
    const __nv_bfloat16* __restrict__ Vh, const __nv_bfloat16* __restrict__ Vl,
    __nv_bfloat16* __restrict__ Yh, __nv_bfloat16* __restrict__ Yl)
{
    extern __shared__ char fsm[];
    const uint32_t sb  = smem_u32(fsm);
    const uint32_t sQH = sb;
    const uint32_t sQL = sb + FQB;
    const uint32_t sKV = sb + 2 * FQB;

    const int qt = blockIdx.x, h = blockIdx.y, b = blockIdx.z;
    const int tid = threadIdx.x, wid = tid >> 5, lane = tid & 31;
    const int wm = wid * 16;
    const int lr = lane & 15;
    const int lcg = (lane >> 4) << 3;

    const int ccf = tid & 15;
    const int r0f = tid >> 4;

    {
        const __nv_bfloat16* qh_g = Qh + ((size_t)(b * T_ + qt * 128)) * ATTN_ + h * D_;
        const __nv_bfloat16* ql_g = Ql + ((size_t)(b * T_ + qt * 128)) * ATTN_ + h * D_;
#pragma unroll
        for (int bb = 0; bb < 8; bb++) {
            const int r = bb * 16 + r0f;
            const uint32_t so = r * (FLD * 2) + ccf * 16;
            const size_t go = (size_t)r * ATTN_ + ccf * 8;
            CP_ASYNC16(sQH + so, qh_g + go);
            CP_ASYNC16(sQL + so, ql_g + go);
        }
        CP_COMMIT();
    }

    const int nkv = 2 * qt + 2;

    auto issue_kv = [&](int j) {
        const uint32_t st = sKV + (j & 1) * FSTG;
        const size_t base = ((size_t)(b * T_ + j * 64)) * ATTN_ + h * D_;
#pragma unroll
        for (int bb = 0; bb < 4; bb++) {
            const int r = bb * 16 + r0f;
            const uint32_t so = r * (FLD * 2) + ccf * 16;
            const size_t go = base + (size_t)r * ATTN_ + ccf * 8;
            CP_ASYNC16(st + so, Kh + go);
            CP_ASYNC16(st + FKB + so, Kl + go);
            CP_ASYNC16(st + 2 * FKB + so, Vh + go);
            CP_ASYNC16(st + 3 * FKB + so, Vl + go);
        }
        CP_COMMIT();
    };

    issue_kv(0);

    float Oacc[16][4];
#pragma unroll
    for (int nt = 0; nt < 16; nt++)
#pragma unroll
        for (int e = 0; e < 4; e++) Oacc[nt][e] = 0.f;
    float m0 = -1e30f, m1 = -1e30f, l0 = 0.f, l1 = 0.f;

    const int grow0 = qt * 128 + wm + (lane >> 2);
    const int grow1 = grow0 + 8;

    for (int j = 0; j < nkv; j++) {
        if (j + 1 < nkv) {
            issue_kv(j + 1);
            CP_WAIT(1);
        } else {
            CP_WAIT(0);
        }
        __syncthreads();

        const uint32_t st  = sKV + (j & 1) * FSTG;
        const uint32_t cKH = st;
        const uint32_t cKL = st + FKB;
        const uint32_t cVH = st + 2 * FKB;
        const uint32_t cVL = st + 3 * FKB;

        float sc[8][4];
#pragma unroll
        for (int nt = 0; nt < 8; nt++)
#pragma unroll
            for (int e = 0; e < 4; e++) sc[nt][e] = 0.f;

#pragma unroll 2
        for (int ks = 0; ks < 8; ks++) {
            const int kc = ks * 16 + lcg;
            uint32_t aQh[4], aQl[4], kh[4][4], kl[4][4];
            ldsm4(aQh, sQH + ((wm + lr) * FLD + kc) * 2);
            ldsm4(aQl, sQL + ((wm + lr) * FLD + kc) * 2);
#pragma unroll
            for (int g = 0; g < 4; g++) {
                ldsm4(kh[g], cKH + ((g * 16 + lr) * FLD + kc) * 2);
                ldsm4(kl[g], cKL + ((g * 16 + lr) * FLD + kc) * 2);
            }
#pragma unroll
            for (int nt = 0; nt < 8; nt++) {
                const uint32_t b0h = kh[nt >> 1][nt & 1], b1h = kh[nt >> 1][(nt & 1) + 2];
                mma16816(sc[nt], aQh, b0h, b1h);
                mma16816(sc[nt], aQh, kl[nt >> 1][nt & 1], kl[nt >> 1][(nt & 1) + 2]);
                mma16816(sc[nt], aQl, b0h, b1h);
            }
        }

        if (j >= 2 * qt) {
            const int c0 = j * 64 + ((lane & 3) << 1);
#pragma unroll
            for (int nt = 0; nt < 8; nt++) {
                const int gc = c0 + nt * 8;
                if (gc > grow0)     sc[nt][0] = -1e30f;
                if (gc + 1 > grow0) sc[nt][1] = -1e30f;
                if (gc > grow1)     sc[nt][2] = -1e30f;
                if (gc + 1 > grow1) sc[nt][3] = -1e30f;
            }
        }
        float mx0 = -1e30f, mx1 = -1e30f;
#pragma unroll
        for (int nt = 0; nt < 8; nt++) {
            mx0 = fmaxf(mx0, fmaxf(sc[nt][0], sc[nt][1]));
            mx1 = fmaxf(mx1, fmaxf(sc[nt][2], sc[nt][3]));
        }
        mx0 = fmaxf(mx0, __shfl_xor_sync(0xffffffffu, mx0, 1));
        mx0 = fmaxf(mx0, __shfl_xor_sync(0xffffffffu, mx0, 2));
        mx1 = fmaxf(mx1, __shfl_xor_sync(0xffffffffu, mx1, 1));
        mx1 = fmaxf(mx1, __shfl_xor_sync(0xffffffffu, mx1, 2));
        const float mn0 = fmaxf(m0, mx0), mn1 = fmaxf(m1, mx1);
        const float al0 = __expf(m0 - mn0), al1 = __expf(m1 - mn1);
        float ls0 = 0.f, ls1 = 0.f;
#pragma unroll
        for (int nt = 0; nt < 8; nt++) {
            sc[nt][0] = __expf(sc[nt][0] - mn0);
            sc[nt][1] = __expf(sc[nt][1] - mn0);
            sc[nt][2] = __expf(sc[nt][2] - mn1);
            sc[nt][3] = __expf(sc[nt][3] - mn1);
            ls0 += sc[nt][0] + sc[nt][1];
            ls1 += sc[nt][2] + sc[nt][3];
        }
        ls0 += __shfl_xor_sync(0xffffffffu, ls0, 1);
        ls0 += __shfl_xor_sync(0xffffffffu, ls0, 2);
        ls1 += __shfl_xor_sync(0xffffffffu, ls1, 1);
        ls1 += __shfl_xor_sync(0xffffffffu, ls1, 2);
        l0 = l0 * al0 + ls0; m0 = mn0;
        l1 = l1 * al1 + ls1; m1 = mn1;
#pragma unroll
        for (int nt = 0; nt < 16; nt++) {
            Oacc[nt][0] *= al0; Oacc[nt][1] *= al0;
            Oacc[nt][2] *= al1; Oacc[nt][3] *= al1;
        }

#pragma unroll
        for (int ks = 0; ks < 4; ks++) {
            uint32_t aPh[4], aPl[4];
            {
                const float p0 = sc[2 * ks][0],     p1 = sc[2 * ks][1];
                const float p2 = sc[2 * ks][2],     p3 = sc[2 * ks][3];
                const float p4 = sc[2 * ks + 1][0], p5 = sc[2 * ks + 1][1];
                const float p6 = sc[2 * ks + 1][2], p7 = sc[2 * ks + 1][3];
                aPh[0] = packbf2(p0, p1);
                aPh[1] = packbf2(p2, p3);
                aPh[2] = packbf2(p4, p5);
                aPh[3] = packbf2(p6, p7);
                aPl[0] = packbf2(p0 - __bfloat162float(__float2bfloat16(p0)),
                                 p1 - __bfloat162float(__float2bfloat16(p1)));
                aPl[1] = packbf2(p2 - __bfloat162float(__float2bfloat16(p2)),
                                 p3 - __bfloat162float(__float2bfloat16(p3)));
                aPl[2] = packbf2(p4 - __bfloat162float(__float2bfloat16(p4)),
                                 p5 - __bfloat162float(__float2bfloat16(p5)));
                aPl[3] = packbf2(p6 - __bfloat162float(__float2bfloat16(p6)),
                                 p7 - __bfloat162float(__float2bfloat16(p7)));
            }
#pragma unroll
            for (int ng = 0; ng < 8; ng++) {
                uint32_t bh[4], bl[4];
                const uint32_t va = ((ks * 16 + lr) * FLD + ng * 16 + lcg) * 2;
                ldsm4t(bh, cVH + va);
                ldsm4t(bl, cVL + va);
                mma16816(Oacc[2 * ng], aPh, bh[0], bh[1]);
                mma16816(Oacc[2 * ng], aPh, bl[0], bl[1]);
                mma16816(Oacc[2 * ng], aPl, bh[0], bh[1]);
                mma16816(Oacc[2 * ng + 1], aPh, bh[2], bh[3]);
                mma16816(Oacc[2 * ng + 1], aPh, bl[2], bl[3]);
                mma16816(Oacc[2 * ng + 1], aPl, bh[2], bh[3]);
            }
        }
        __syncthreads();
    }

    const float inv0 = 1.0f / l0, inv1 = 1.0f / l1;
    const size_t rb0 = ((size_t)(b * T_) + grow0) * ATTN_ + h * D_;
    const size_t rb1 = ((size_t)(b * T_) + grow1) * ATTN_ + h * D_;
    const int nn = (lane & 3) << 1;
#pragma unroll
    for (int nt = 0; nt < 16; nt++) {
        const int col = nt * 8 + nn;
        {
            const float v0 = Oacc[nt][0] * inv0, v1 = Oacc[nt][1] * inv0;
            const __nv_bfloat16 h0 = __float2bfloat16(v0), h1 = __float2bfloat16(v1);
            *(__nv_bfloat162*)(Yh + rb0 + col) = __halves2bfloat162(h0, h1);
            *(__nv_bfloat162*)(Yl + rb0 + col) = __halves2bfloat162(
                __float2bfloat16(v0 - __bfloat162float(h0)),
                __float2bfloat16(v1 - __bfloat162float(h1)));
        }
        {
            const float v0 = Oacc[nt][2] * inv1, v1 = Oacc[nt][3] * inv1;
            const __nv_bfloat16 h0 = __float2bfloat16(v0), h1 = __float2bfloat16(v1);
            *(__nv_bfloat162*)(Yh + rb1 + col) = __halves2bfloat162(h0, h1);
            *(__nv_bfloat162*)(Yl + rb1 + col) = __halves2bfloat162(
                __float2bfloat16(v0 - __bfloat162float(h0)),
                __float2bfloat16(v1 - __bfloat162float(h1)));
        }
    }
}

// ---------------------------------------------------------------------------
// Host side. Launch order matters: ncu captures launch #5 = out_gemm.
// ---------------------------------------------------------------------------
extern "C" void kernel_launch(void* const* d_in, const int* in_sizes, int n_in,
                              void* d_out, int out_size)
{
    const float* x    = (const float*)d_in[0];
    const float* wq_w = (const float*)d_in[3];
    const float* wq_b = (const float*)d_in[4];
    const float* wk_w = (const float*)d_in[5];
    const float* wk_b = (const float*)d_in[6];
    const float* wv_w = (const float*)d_in[7];
    const float* wv_b = (const float*)d_in[8];
    const float* wo_w = (const float*)d_in[9];
    const float* wo_b = (const float*)d_in[10];
    float* out = (float*)d_out;

    float *cosp, *sinp;
    __nv_bfloat16 *xh, *xl, *qh, *ql, *kh, *kl, *vh, *vl, *yh, *yl, *wh, *wl;
    cudaGetSymbolAddress((void**)&cosp, g_cosT);
    cudaGetSymbolAddress((void**)&sinp, g_sinT);
    cudaGetSymbolAddress((void**)&xh, g_xh);
    cudaGetSymbolAddress((void**)&xl, g_xl);
    cudaGetSymbolAddress((void**)&qh, g_qh);
    cudaGetSymbolAddress((void**)&ql, g_ql);
    cudaGetSymbolAddress((void**)&kh, g_kh);
    cudaGetSymbolAddress((void**)&kl, g_kl);
    cudaGetSymbolAddress((void**)&vh, g_vh);
    cudaGetSymbolAddress((void**)&vl, g_vl);
    cudaGetSymbolAddress((void**)&yh, g_yh);
    cudaGetSymbolAddress((void**)&yl, g_yl);
    cudaGetSymbolAddress((void**)&wh, g_wh);
    cudaGetSymbolAddress((void**)&wl, g_wl);

    const size_t WSZ = (size_t)ATTN_ * ATTN_;

    // #0
    rope_table_kernel<<<T_, 64>>>(cosp, sinp);
    // #1
    const int n4x = BT_ * ATTN_ / 4;
    split_kernel<<<n4x / 256, 256>>>((const float4*)x, (__nv_bfloat162*)xh,
                                     (__nv_bfloat162*)xl, n4x);
    // #2 : all 4 weight matrices, one launch
    const int n4w = ATTN_ * ATTN_ / 4;
    split_w_kernel<<<dim3(n4w / 256, 1, 4), 256>>>(wq_w, wk_w, wv_w, wo_w,
                                                   (__nv_bfloat162*)wh,
                                                   (__nv_bfloat162*)wl, n4w);

    cudaFuncSetAttribute(qkv_gemm, cudaFuncAttributeMaxDynamicSharedMemorySize, GEMM_SMEM);
    cudaFuncSetAttribute(out_gemm, cudaFuncAttributeMaxDynamicSharedMemorySize, GEMM_SMEM);
    cudaFuncSetAttribute(flash_mma, cudaFuncAttributeMaxDynamicSharedMemorySize, FSMEM);

    // #3 : fused QKV
    qkv_gemm<<<dim3(24, BT_ / GBM), 256, GEMM_SMEM>>>(xh, xl, wh, wl,
                                                      wq_b, wk_b, wv_b,
                                                      qh, ql, kh, kl, vh, vl,
                                                      cosp, sinp);
    // #4 : attention
    flash_mma<<<dim3(T_ / 128, H_, B_), 256, FSMEM>>>(qh, ql, kh, kl, vh, vl, yh, yl);

    // #5 : output projection (ncu capture target)
    out_gemm<<<dim3(ATTN_ / GBN, BT_ / GBM), 256, GEMM_SMEM>>>(yh, yl,
                                                               wh + 3 * WSZ, wl + 3 * WSZ,
                                                               wo_b, out);
}